// round 10
// baseline (speedup 1.0000x reference)
#include <cuda_runtime.h>
#include <cuda_bf16.h>
#include <math.h>
#include <float.h>
#include <stdint.h>

#define BATCH 2
#define SEQ   2048
#define DIM   1024
#define NH    16
#define DH    64
#define WIN   512
#define E3    3072
#define MTOT  (BATCH * SEQ)   // 4096
#define KD    1024

// ---------------- scratch (device globals; no allocation) ------------------
__device__ signed char  g_xa1[MTOT * KD], g_xa0[MTOT * KD];    // x int8 limbs
__device__ signed char  g_wq1[E3 * KD],   g_wq0[E3 * KD];      // Wqkv^T limbs
__device__ __nv_bfloat16 g_woh[DIM * KD], g_wol[DIM * KD];     // Wout^T bf16 split
__device__ __nv_bfloat16 g_qh[MTOT * E3], g_ql[MTOT * E3];     // split qkv (bf16)
__device__ __nv_bfloat16 g_ch[MTOT * KD], g_cl[MTOT * KD];     // split ctx (bf16)

// quantization: value = (l1*128 + l0) * s ; s_x covers +-6.5, s_w covers +-0.2
#define ISX (16384.0f / 6.5f)
#define ISW (16384.0f / 0.2f)
#define SXW (6.5f * 0.2f / (16384.0f * 16384.0f))
#define DQ1 (SXW * 16384.0f)
#define DQX (SXW * 128.0f)
#define DQZ (SXW)

// ---------------- helpers ---------------------------------------------------
__device__ __forceinline__ uint32_t pack_bf16(float lo, float hi) {
    uint32_t r;
    asm("cvt.rn.bf16x2.f32 %0, %1, %2;" : "=r"(r) : "f"(hi), "f"(lo));
    return r;
}
__device__ __forceinline__ void split_pair(float x, float y, uint32_t& hi, uint32_t& lo) {
    hi = pack_bf16(x, y);
    float xh = __uint_as_float(hi << 16);
    float yh = __uint_as_float(hi & 0xFFFF0000u);
    lo = pack_bf16(x - xh, y - yh);
}
__device__ __forceinline__ void mma_bf16(float* c, const uint32_t* a, const uint32_t* b) {
    asm volatile(
        "mma.sync.aligned.m16n8k16.row.col.f32.bf16.bf16.f32 "
        "{%0,%1,%2,%3}, {%4,%5,%6,%7}, {%8,%9}, {%0,%1,%2,%3};"
        : "+f"(c[0]), "+f"(c[1]), "+f"(c[2]), "+f"(c[3])
        : "r"(a[0]), "r"(a[1]), "r"(a[2]), "r"(a[3]), "r"(b[0]), "r"(b[1]));
}
__device__ __forceinline__ void mma_s8(int* c, const uint32_t* a, const uint32_t* b) {
    asm volatile(
        "mma.sync.aligned.m16n8k32.row.col.s32.s8.s8.s32 "
        "{%0,%1,%2,%3}, {%4,%5,%6,%7}, {%8,%9}, {%0,%1,%2,%3};"
        : "+r"(c[0]), "+r"(c[1]), "+r"(c[2]), "+r"(c[3])
        : "r"(a[0]), "r"(a[1]), "r"(a[2]), "r"(a[3]), "r"(b[0]), "r"(b[1]));
}
__device__ __forceinline__ uint32_t smem_u32(const void* p) {
    return (uint32_t)__cvta_generic_to_shared(p);
}
#define CP16(s, g) \
    asm volatile("cp.async.cg.shared.global [%0], [%1], 16;" :: "r"(s), "l"(g))
#define CP_COMMIT() asm volatile("cp.async.commit_group;")
#define CP_WAIT(n)  asm volatile("cp.async.wait_group %0;" :: "n"(n))
#define LDSM4(r, a) \
    asm volatile("ldmatrix.sync.aligned.m8n8.x4.shared.b16 {%0,%1,%2,%3}, [%4];" \
        : "=r"((r)[0]), "=r"((r)[1]), "=r"((r)[2]), "=r"((r)[3]) : "r"(a))
#define LDSM4T(r, a) \
    asm volatile("ldmatrix.sync.aligned.m8n8.x4.trans.shared.b16 {%0,%1,%2,%3}, [%4];" \
        : "=r"((r)[0]), "=r"((r)[1]), "=r"((r)[2]), "=r"((r)[3]) : "r"(a))

// ---------------------------------------------------------------------------
// Prep kernels
// ---------------------------------------------------------------------------
__device__ __forceinline__ void q15(float v, float inv_s, signed char& l1, signed char& l0) {
    float t = v * inv_s;
    float a1 = rintf(t * 0.0078125f);                // /128
    a1 = fminf(127.f, fmaxf(-127.f, a1));
    float a0 = rintf(t - a1 * 128.f);
    a0 = fminf(127.f, fmaxf(-127.f, a0));
    l1 = (signed char)(int)a1;
    l0 = (signed char)(int)a0;
}

__global__ __launch_bounds__(256) void quant_x_kernel(
    const float* __restrict__ x, signed char* __restrict__ xa1,
    signed char* __restrict__ xa0)
{
    int i = blockIdx.x * 256 + threadIdx.x;
    float4 v = ((const float4*)x)[i];
    char4 c1, c0;
    q15(v.x, ISX, c1.x, c0.x);
    q15(v.y, ISX, c1.y, c0.y);
    q15(v.z, ISX, c1.z, c0.z);
    q15(v.w, ISX, c1.w, c0.w);
    ((char4*)xa1)[i] = c1;
    ((char4*)xa0)[i] = c0;
}

// W[K][N] fp32 -> transposed int8 limbs [N][K]
__global__ __launch_bounds__(256) void quantW_kernel(
    const float* __restrict__ W, signed char* __restrict__ w1,
    signed char* __restrict__ w0, int N, int K)
{
    __shared__ float tile[32][33];
    int tx = threadIdx.x, ty = threadIdx.y;
    int n0 = blockIdx.x * 32, k0 = blockIdx.y * 32;
#pragma unroll
    for (int i = 0; i < 4; i++)
        tile[ty + 8 * i][tx] = W[(long)(k0 + ty + 8 * i) * N + n0 + tx];
    __syncthreads();
#pragma unroll
    for (int i = 0; i < 4; i++) {
        int n = ty + 8 * i;
        signed char l1, l0;
        q15(tile[tx][n], ISW, l1, l0);
        w1[(long)(n0 + n) * K + k0 + tx] = l1;
        w0[(long)(n0 + n) * K + k0 + tx] = l0;
    }
}

// W[K][N] fp32 -> Wt hi/lo [N][K] bf16 (for GEMM3)
__global__ __launch_bounds__(256) void tsplit_kernel(
    const float* __restrict__ W, __nv_bfloat16* __restrict__ Wth,
    __nv_bfloat16* __restrict__ Wtl, int N, int K)
{
    __shared__ float tile[32][33];
    int tx = threadIdx.x, ty = threadIdx.y;
    int n0 = blockIdx.x * 32, k0 = blockIdx.y * 32;
#pragma unroll
    for (int i = 0; i < 4; i++)
        tile[ty + 8 * i][tx] = W[(long)(k0 + ty + 8 * i) * N + n0 + tx];
    __syncthreads();
#pragma unroll
    for (int i = 0; i < 4; i++) {
        int n = ty + 8 * i;
        float v = tile[tx][n];
        __nv_bfloat16 h = __float2bfloat16(v);
        Wth[(long)(n0 + n) * K + k0 + tx] = h;
        Wtl[(long)(n0 + n) * K + k0 + tx] = __float2bfloat16(v - __bfloat162float(h));
    }
}

// ---------------------------------------------------------------------------
// GEMM1 (int8 dual-limb IMMA): qkv = x @ Wqkv -> bf16 hi/lo (Q cols scaled).
// CTA 128(m) x 64(n), BK=32, 512 thr = 16 warps (4m x 4n of 32x16 warp tiles).
// 4 limb passes per k-tile into separate s32 accumulators.
// ---------------------------------------------------------------------------
#define ILD   48                         // smem row stride bytes (32 used)
#define IA_B  (128 * ILD)                // 6144 per A limb
#define IB_B  (64 * ILD)                 // 3072 per B limb
#define ISTG  (2 * IA_B + 2 * IB_B)      // 18432
#define I_SMEM (2 * ISTG)                // 36864

__global__ __launch_bounds__(512) void gemm1_imma(
    const signed char* __restrict__ Xa1, const signed char* __restrict__ Xa0,
    const signed char* __restrict__ Wb1, const signed char* __restrict__ Wb0,
    __nv_bfloat16* __restrict__ Ch, __nv_bfloat16* __restrict__ Cl)
{
    extern __shared__ char smem[];
    const uint32_t sb = smem_u32(smem);
    const int tid = threadIdx.x, wid = tid >> 5, lane = tid & 31;
    const int wm = (wid & 3) * 32, wn = (wid >> 2) * 16;
    const long arow0 = (long)blockIdx.y * 128;
    const long brow0 = (long)blockIdx.x * 64;
    const int K = KD, N = E3;

    int accA[2][2][4] = {};   // a1*w1  (weight 2^14)
    int accB[2][2][4] = {};   // a1*w0  (weight 2^7)
    int accC[2][2][4] = {};   // a0*w1  (weight 2^7)
    int accD[2][2][4] = {};   // a0*w0  (weight 1)

    const uint32_t a_off = (uint32_t)((wm + (lane & 15)) * ILD
                                      + ((lane & 16) ? 16 : 0));
    const uint32_t b_off = (uint32_t)(2 * IA_B
                   + (wn + (lane & 7) + ((lane & 16) ? 8 : 0)) * ILD
                   + ((lane & 8) ? 16 : 0));

    auto issue = [&](int t) {
        const int s = t & 1, k0 = t * 32;
        const uint32_t st = sb + s * ISTG;
        // A limbs: 256 chunks each; 512 threads cover hi+lo
        {
            int idx = tid & 255, limb = tid >> 8;
            int r = idx >> 1, h = idx & 1;
            uint32_t so = st + limb * IA_B + r * ILD + h * 16;
            long go = (arow0 + r) * K + k0 + h * 16;
            CP16(so, (limb ? Xa0 : Xa1) + go);
        }
        // B limbs: 128 chunks each; threads 0-255 cover hi+lo
        if (tid < 256) {
            int limb = tid >> 7, t2 = tid & 127;
            int r = t2 >> 1, h = t2 & 1;
            uint32_t so = st + 2 * IA_B + limb * IB_B + r * ILD + h * 16;
            long go = (brow0 + r) * K + k0 + h * 16;
            CP16(so, (limb ? Wb0 : Wb1) + go);
        }
        CP_COMMIT();
    };

    issue(0);
    const int nT = K / 32;
    for (int t = 0; t < nT; t++) {
        if (t + 1 < nT) { issue(t + 1); CP_WAIT(1); }
        else            { CP_WAIT(0); }
        __syncthreads();

        const uint32_t st = sb + (t & 1) * ISTG;
        // B fragments: one x4 per limb covers the warp's 16 n-rows x k32
        uint32_t w1f[4], w0f[4];
        LDSM4(w1f, st + b_off);
        LDSM4(w0f, st + IB_B + b_off);
        // A fragments per 16-row block, both limbs
        uint32_t a1f[2][4], a0f[2][4];
#pragma unroll
        for (int am = 0; am < 2; am++) {
            uint32_t a = st + a_off + am * (16 * ILD);
            LDSM4(a1f[am], a);
            LDSM4(a0f[am], a + IA_B);
        }
        // pass-major: 4 independent accumulator groups, RAW distance 4 each
#pragma unroll
        for (int am = 0; am < 2; am++)
#pragma unroll
            for (int bn = 0; bn < 2; bn++)
                mma_s8(accA[am][bn], a1f[am], &w1f[bn * 2]);
#pragma unroll
        for (int am = 0; am < 2; am++)
#pragma unroll
            for (int bn = 0; bn < 2; bn++)
                mma_s8(accB[am][bn], a1f[am], &w0f[bn * 2]);
#pragma unroll
        for (int am = 0; am < 2; am++)
#pragma unroll
            for (int bn = 0; bn < 2; bn++)
                mma_s8(accC[am][bn], a0f[am], &w1f[bn * 2]);
#pragma unroll
        for (int am = 0; am < 2; am++)
#pragma unroll
            for (int bn = 0; bn < 2; bn++)
                mma_s8(accD[am][bn], a0f[am], &w0f[bn * 2]);
        __syncthreads();
    }

    // epilogue: dequant, scale Q columns, split to bf16 hi/lo
#pragma unroll
    for (int am = 0; am < 2; am++)
#pragma unroll
        for (int bn = 0; bn < 2; bn++) {
            int row = blockIdx.y * 128 + wm + am * 16 + (lane >> 2);
            int col = blockIdx.x * 64 + wn + bn * 8 + 2 * (lane & 3);
            float c[4];
#pragma unroll
            for (int j = 0; j < 4; j++)
                c[j] = DQ1 * (float)accA[am][bn][j]
                     + DQX * ((float)accB[am][bn][j] + (float)accC[am][bn][j])
                     + DQZ * (float)accD[am][bn][j];
            float scl = (col < DIM) ? 0.125f : 1.0f;
            uint32_t hh, ll;
            split_pair(c[0] * scl, c[1] * scl, hh, ll);
            *(uint32_t*)(Ch + (long)row * N + col) = hh;
            *(uint32_t*)(Cl + (long)row * N + col) = ll;
            split_pair(c[2] * scl, c[3] * scl, hh, ll);
            *(uint32_t*)(Ch + (long)(row + 8) * N + col) = hh;
            *(uint32_t*)(Cl + (long)(row + 8) * N + col) = ll;
        }
}

// ---------------------------------------------------------------------------
// GEMM3 (bf16x3, R7-proven): out = ctx @ Wout, fp32 C.
// Block tile 128x128, BK=32, 256 thr = 8 warps (2m x 4n of 64x32), 2 CTA/SM.
// ---------------------------------------------------------------------------
#define LDT      40
#define A_BYTES  (128 * LDT * 2)
#define B_BYTES  (128 * LDT * 2)
#define STG      (2 * A_BYTES + 2 * B_BYTES)
#define GEMM_SMEM (2 * STG)

__global__ __launch_bounds__(256, 2) void gemm3_bf16(
    const __nv_bfloat16* __restrict__ Ah, const __nv_bfloat16* __restrict__ Al,
    const __nv_bfloat16* __restrict__ Bh, const __nv_bfloat16* __restrict__ Bl,
    float* __restrict__ Cf, int M, int N, int K)
{
    extern __shared__ char smem[];
    const uint32_t sb = smem_u32(smem);
    const int tid = threadIdx.x, wid = tid >> 5, lane = tid & 31;
    const int wm = (wid & 1) * 64, wn = (wid >> 1) * 32;
    const long arow0 = (long)blockIdx.y * 128;
    const long brow0 = (long)blockIdx.x * 128;

    float acc[4][4][4] = {};

    const uint32_t a_off =
        (uint32_t)((wm + (lane & 7) + ((lane & 8) ? 8 : 0)) * (LDT * 2)
                   + ((lane & 16) ? 16 : 0));
    const uint32_t b_off = (uint32_t)(2 * A_BYTES
                   + (wn + (lane & 7) + ((lane & 16) ? 8 : 0)) * (LDT * 2)
                   + ((lane & 8) ? 16 : 0));

    const int nT = K / 32;

    auto issue = [&](int t) {
        const int s = t & 1, k0 = t * 32;
        const uint32_t st = sb + s * STG;
#pragma unroll
        for (int i = 0; i < 2; i++) {
            int idx = i * 256 + tid;
            int row = idx >> 2, kc = idx & 3;
            uint32_t so = st + row * (LDT * 2) + kc * 16;
            long go = (arow0 + row) * K + k0 + kc * 8;
            CP16(so, Ah + go);
            CP16(so + A_BYTES, Al + go);
        }
#pragma unroll
        for (int i = 0; i < 2; i++) {
            int idx = i * 256 + tid;
            int row = idx >> 2, kc = idx & 3;
            uint32_t so = st + 2 * A_BYTES + row * (LDT * 2) + kc * 16;
            long go = (brow0 + row) * K + k0 + kc * 8;
            CP16(so, Bh + go);
            CP16(so + B_BYTES, Bl + go);
        }
        CP_COMMIT();
    };

    issue(0);
    for (int t = 0; t < nT; t++) {
        if (t + 1 < nT) { issue(t + 1); CP_WAIT(1); }
        else            { CP_WAIT(0); }
        __syncthreads();

        const uint32_t st = sb + (t & 1) * STG;
#pragma unroll
        for (int ks = 0; ks < 2; ks++) {
            uint32_t ah[4][4], al[4][4], bh[4][2], bl[4][2];
#pragma unroll
            for (int am = 0; am < 4; am++) {
                uint32_t a = st + a_off + am * (16 * LDT * 2) + ks * 32;
                LDSM4(ah[am], a);
                LDSM4(al[am], a + A_BYTES);
            }
#pragma unroll
            for (int g = 0; g < 2; g++) {
                uint32_t a = st + b_off + g * (16 * LDT * 2) + ks * 32;
                uint32_t r[4];
                LDSM4(r, a);
                bh[2*g][0] = r[0]; bh[2*g][1] = r[1];
                bh[2*g+1][0] = r[2]; bh[2*g+1][1] = r[3];
                LDSM4(r, a + B_BYTES);
                bl[2*g][0] = r[0]; bl[2*g][1] = r[1];
                bl[2*g+1][0] = r[2]; bl[2*g+1][1] = r[3];
            }
#pragma unroll
            for (int am = 0; am < 4; am++)
#pragma unroll
                for (int bn = 0; bn < 4; bn++)
                    mma_bf16(acc[am][bn], al[am], bh[bn]);
#pragma unroll
            for (int am = 0; am < 4; am++)
#pragma unroll
                for (int bn = 0; bn < 4; bn++)
                    mma_bf16(acc[am][bn], ah[am], bl[bn]);
#pragma unroll
            for (int am = 0; am < 4; am++)
#pragma unroll
                for (int bn = 0; bn < 4; bn++)
                    mma_bf16(acc[am][bn], ah[am], bh[bn]);
        }
        __syncthreads();
    }

#pragma unroll
    for (int am = 0; am < 4; am++)
#pragma unroll
        for (int bn = 0; bn < 4; bn++) {
            int row = blockIdx.y * 128 + wm + am * 16 + (lane >> 2);
            int col = blockIdx.x * 128 + wn + bn * 8 + 2 * (lane & 3);
            *(float2*)(Cf + (long)row * N + col) =
                make_float2(acc[am][bn][0], acc[am][bn][1]);
            *(float2*)(Cf + (long)(row + 8) * N + col) =
                make_float2(acc[am][bn][2], acc[am][bn][3]);
        }
}

// ---------------------------------------------------------------------------
// Sliding-window flash attention, bf16 hi/lo 3-pass on mma.sync (R7-proven).
// Inputs pre-split (Q pre-scaled). 128 q-rows/block, 4 warps, key tile 64.
// ---------------------------------------------------------------------------
#define KVP 72   // bf16 per smem row (64 + 8 pad)

__global__ __launch_bounds__(128) void attn_mma(
    const __nv_bfloat16* __restrict__ qh, const __nv_bfloat16* __restrict__ ql,
    __nv_bfloat16* __restrict__ ctxh, __nv_bfloat16* __restrict__ ctxl)
{
    __shared__ __nv_bfloat16 Kh[64 * KVP], Kl[64 * KVP];
    __shared__ __nv_bfloat16 Vh[64 * KVP], Vl[64 * KVP];

    const int tid  = threadIdx.x;
    const int wid  = tid >> 5;
    const int lane = tid & 31;
    const int gid  = lane >> 2;
    const int tig  = lane & 3;
    const int i0   = blockIdx.x * 128;
    const int h    = blockIdx.y;
    const int b    = blockIdx.z;

    const long rowb = (long)b * SEQ;
    const int qcol = h * DH;
    const int kcol = DIM + h * DH;
    const int vcol = 2 * DIM + h * DH;

    uint32_t qfh[2][4][4], qfl[2][4][4];
#pragma unroll
    for (int am = 0; am < 2; am++) {
        long r = rowb + i0 + wid * 32 + am * 16 + gid;
#pragma unroll
        for (int s = 0; s < 4; s++) {
            int c = qcol + s * 16 + 2 * tig;
            qfh[am][s][0] = *(const uint32_t*)(qh + r * E3 + c);
            qfh[am][s][1] = *(const uint32_t*)(qh + (r + 8) * E3 + c);
            qfh[am][s][2] = *(const uint32_t*)(qh + r * E3 + c + 8);
            qfh[am][s][3] = *(const uint32_t*)(qh + (r + 8) * E3 + c + 8);
            qfl[am][s][0] = *(const uint32_t*)(ql + r * E3 + c);
            qfl[am][s][1] = *(const uint32_t*)(ql + (r + 8) * E3 + c);
            qfl[am][s][2] = *(const uint32_t*)(ql + r * E3 + c + 8);
            qfl[am][s][3] = *(const uint32_t*)(ql + (r + 8) * E3 + c + 8);
        }
    }

    const uint32_t kh_b = smem_u32(Kh), kl_b = smem_u32(Kl);
    const uint32_t vh_b = smem_u32(Vh), vl_b = smem_u32(Vl);
    const uint32_t koff = (uint32_t)(((lane & 7) + ((lane & 16) ? 8 : 0)) * (KVP * 2)
                                     + ((lane & 8) ? 16 : 0));
    const uint32_t voff = (uint32_t)(((lane & 7) + ((lane & 8) ? 8 : 0)) * (KVP * 2)
                                     + ((lane & 16) ? 16 : 0));

    float mrow[2][2], lrow[2][2], o[2][8][4] = {};
#pragma unroll
    for (int am = 0; am < 2; am++) {
        mrow[am][0] = -FLT_MAX; mrow[am][1] = -FLT_MAX;
        lrow[am][0] = 0.f;      lrow[am][1] = 0.f;
    }

    int t0 = (i0 - WIN + 1) >> 6; if (t0 < 0) t0 = 0;
    const int t1 = (i0 + 127) >> 6;

    for (int t = t0; t <= t1; t++) {
        const int kt0 = t << 6;
        __syncthreads();

#pragma unroll
        for (int i = 0; i < 4; i++) {
            int idx = i * 128 + tid;
            int row = idx >> 3, ch = idx & 7;
            long gro = (rowb + kt0 + row) * E3;
            uint32_t so = row * (KVP * 2) + ch * 16;
            CP16(kh_b + so, qh + gro + kcol + ch * 8);
            CP16(kl_b + so, ql + gro + kcol + ch * 8);
            CP16(vh_b + so, qh + gro + vcol + ch * 8);
            CP16(vl_b + so, ql + gro + vcol + ch * 8);
        }
        CP_COMMIT();
        CP_WAIT(0);
        __syncthreads();

        float s[2][8][4] = {};
#pragma unroll
        for (int ks = 0; ks < 4; ks++) {
            uint32_t kh[8][2], kl[8][2];
#pragma unroll
            for (int g = 0; g < 4; g++) {
                uint32_t a = koff + g * (16 * KVP * 2) + ks * 32;
                uint32_t r[4];
                LDSM4(r, kh_b + a);
                kh[2*g][0] = r[0]; kh[2*g][1] = r[1];
                kh[2*g+1][0] = r[2]; kh[2*g+1][1] = r[3];
                LDSM4(r, kl_b + a);
                kl[2*g][0] = r[0]; kl[2*g][1] = r[1];
                kl[2*g+1][0] = r[2]; kl[2*g+1][1] = r[3];
            }
#pragma unroll
            for (int bn = 0; bn < 8; bn++)
#pragma unroll
                for (int am = 0; am < 2; am++)
                    mma_bf16(s[am][bn], qfl[am][ks], kh[bn]);
#pragma unroll
            for (int bn = 0; bn < 8; bn++)
#pragma unroll
                for (int am = 0; am < 2; am++)
                    mma_bf16(s[am][bn], qfh[am][ks], kl[bn]);
#pragma unroll
            for (int bn = 0; bn < 8; bn++)
#pragma unroll
                for (int am = 0; am < 2; am++)
                    mma_bf16(s[am][bn], qfh[am][ks], kh[bn]);
        }

#pragma unroll
        for (int am = 0; am < 2; am++) {
            int qi0 = i0 + wid * 32 + am * 16 + gid;
            int qi1 = qi0 + 8;
#pragma unroll
            for (int bn = 0; bn < 8; bn++) {
                int c0 = kt0 + bn * 8 + 2 * tig, c1 = c0 + 1;
                if (c0 > qi0 || c0 < qi0 - (WIN - 1)) s[am][bn][0] = -FLT_MAX;
                if (c1 > qi0 || c1 < qi0 - (WIN - 1)) s[am][bn][1] = -FLT_MAX;
                if (c0 > qi1 || c0 < qi1 - (WIN - 1)) s[am][bn][2] = -FLT_MAX;
                if (c1 > qi1 || c1 < qi1 - (WIN - 1)) s[am][bn][3] = -FLT_MAX;
            }
            float mx0 = -FLT_MAX, mx1 = -FLT_MAX;
#pragma unroll
            for (int bn = 0; bn < 8; bn++) {
                mx0 = fmaxf(mx0, fmaxf(s[am][bn][0], s[am][bn][1]));
                mx1 = fmaxf(mx1, fmaxf(s[am][bn][2], s[am][bn][3]));
            }
            mx0 = fmaxf(mx0, __shfl_xor_sync(0xffffffffu, mx0, 1));
            mx0 = fmaxf(mx0, __shfl_xor_sync(0xffffffffu, mx0, 2));
            mx1 = fmaxf(mx1, __shfl_xor_sync(0xffffffffu, mx1, 1));
            mx1 = fmaxf(mx1, __shfl_xor_sync(0xffffffffu, mx1, 2));
            float mn0 = fmaxf(mrow[am][0], mx0);
            float mn1 = fmaxf(mrow[am][1], mx1);
            float a0 = __expf(mrow[am][0] - mn0);
            float a1 = __expf(mrow[am][1] - mn1);
            mrow[am][0] = mn0; mrow[am][1] = mn1;
            float rs0 = 0.f, rs1 = 0.f;
#pragma unroll
            for (int bn = 0; bn < 8; bn++) {
                s[am][bn][0] = __expf(s[am][bn][0] - mn0);
                s[am][bn][1] = __expf(s[am][bn][1] - mn0);
                s[am][bn][2] = __expf(s[am][bn][2] - mn1);
                s[am][bn][3] = __expf(s[am][bn][3] - mn1);
                rs0 += s[am][bn][0] + s[am][bn][1];
                rs1 += s[am][bn][2] + s[am][bn][3];
            }
            rs0 += __shfl_xor_sync(0xffffffffu, rs0, 1);
            rs0 += __shfl_xor_sync(0xffffffffu, rs0, 2);
            rs1 += __shfl_xor_sync(0xffffffffu, rs1, 1);
            rs1 += __shfl_xor_sync(0xffffffffu, rs1, 2);
            lrow[am][0] = lrow[am][0] * a0 + rs0;
            lrow[am][1] = lrow[am][1] * a1 + rs1;
#pragma unroll
            for (int bn = 0; bn < 8; bn++) {
                o[am][bn][0] *= a0; o[am][bn][1] *= a0;
                o[am][bn][2] *= a1; o[am][bn][3] *= a1;
            }
        }

        uint32_t pf[2][4][4], pg[2][4][4];
#pragma unroll
        for (int am = 0; am < 2; am++)
#pragma unroll
            for (int kk = 0; kk < 4; kk++) {
                split_pair(s[am][2*kk][0],   s[am][2*kk][1],   pf[am][kk][0], pg[am][kk][0]);
                split_pair(s[am][2*kk][2],   s[am][2*kk][3],   pf[am][kk][1], pg[am][kk][1]);
                split_pair(s[am][2*kk+1][0], s[am][2*kk+1][1], pf[am][kk][2], pg[am][kk][2]);
                split_pair(s[am][2*kk+1][2], s[am][2*kk+1][3], pf[am][kk][3], pg[am][kk][3]);
            }

#pragma unroll
        for (int kk = 0; kk < 4; kk++) {
            uint32_t vh[8][2], vl[8][2];
#pragma unroll
            for (int g = 0; g < 4; g++) {
                uint32_t a = voff + kk * (16 * KVP * 2) + g * 32;
                uint32_t r[4];
                LDSM4T(r, vh_b + a);
                vh[2*g][0] = r[0]; vh[2*g][1] = r[1];
                vh[2*g+1][0] = r[2]; vh[2*g+1][1] = r[3];
                LDSM4T(r, vl_b + a);
                vl[2*g][0] = r[0]; vl[2*g][1] = r[1];
                vl[2*g+1][0] = r[2]; vl[2*g+1][1] = r[3];
            }
#pragma unroll
            for (int bn = 0; bn < 8; bn++)
#pragma unroll
                for (int am = 0; am < 2; am++)
                    mma_bf16(o[am][bn], pg[am][kk], vh[bn]);
#pragma unroll
            for (int bn = 0; bn < 8; bn++)
#pragma unroll
                for (int am = 0; am < 2; am++)
                    mma_bf16(o[am][bn], pf[am][kk], vl[bn]);
#pragma unroll
            for (int bn = 0; bn < 8; bn++)
#pragma unroll
                for (int am = 0; am < 2; am++)
                    mma_bf16(o[am][bn], pf[am][kk], vh[bn]);
        }
    }

#pragma unroll
    for (int am = 0; am < 2; am++) {
        float inv0 = 1.f / lrow[am][0];
        float inv1 = 1.f / lrow[am][1];
        long r0 = rowb + i0 + wid * 32 + am * 16 + gid;
#pragma unroll
        for (int bn = 0; bn < 8; bn++) {
            int col = h * DH + bn * 8 + 2 * tig;
            uint32_t hh, ll;
            split_pair(o[am][bn][0] * inv0, o[am][bn][1] * inv0, hh, ll);
            *(uint32_t*)(ctxh + r0 * DIM + col) = hh;
            *(uint32_t*)(ctxl + r0 * DIM + col) = ll;
            split_pair(o[am][bn][2] * inv1, o[am][bn][3] * inv1, hh, ll);
            *(uint32_t*)(ctxh + (r0 + 8) * DIM + col) = hh;
            *(uint32_t*)(ctxl + (r0 + 8) * DIM + col) = ll;
        }
    }
}

// ---------------------------------------------------------------------------
extern "C" void kernel_launch(void* const* d_in, const int* in_sizes, int n_in,
                              void* d_out, int out_size)
{
    (void)in_sizes; (void)n_in; (void)out_size;
    const float* x    = (const float*)d_in[0];
    const float* Wqkv = (const float*)d_in[1];
    const float* Wout = (const float*)d_in[2];
    float* out = (float*)d_out;

    signed char *xa1, *xa0, *wq1, *wq0;
    __nv_bfloat16 *woh, *wol, *qh, *ql, *ch, *cl;
    cudaGetSymbolAddress((void**)&xa1, g_xa1);
    cudaGetSymbolAddress((void**)&xa0, g_xa0);
    cudaGetSymbolAddress((void**)&wq1, g_wq1);
    cudaGetSymbolAddress((void**)&wq0, g_wq0);
    cudaGetSymbolAddress((void**)&woh, g_woh);
    cudaGetSymbolAddress((void**)&wol, g_wol);
    cudaGetSymbolAddress((void**)&qh,  g_qh);
    cudaGetSymbolAddress((void**)&ql,  g_ql);
    cudaGetSymbolAddress((void**)&ch,  g_ch);
    cudaGetSymbolAddress((void**)&cl,  g_cl);

    cudaFuncSetAttribute(gemm1_imma,
                         cudaFuncAttributeMaxDynamicSharedMemorySize, I_SMEM);
    cudaFuncSetAttribute(gemm3_bf16,
                         cudaFuncAttributeMaxDynamicSharedMemorySize, GEMM_SMEM);

    // prep: quantize x + Wqkv (int8 limbs), split Wout (bf16 hi/lo)
    quant_x_kernel<<<(MTOT * KD) / 1024, 256>>>(x, xa1, xa0);
    quantW_kernel<<<dim3(E3 / 32, KD / 32), dim3(32, 8)>>>(Wqkv, wq1, wq0, E3, KD);
    tsplit_kernel<<<dim3(DIM / 32, KD / 32), dim3(32, 8)>>>(Wout, woh, wol, DIM, KD);

    // 1) QKV projection (int8 IMMA) -> split bf16 qkv (Q cols pre-scaled)
    gemm1_imma<<<dim3(E3 / 64, MTOT / 128), 512, I_SMEM>>>(
        xa1, xa0, wq1, wq0, qh, ql);

    // 2) sliding-window attention -> split bf16 ctx
    attn_mma<<<dim3(SEQ / 128, NH, BATCH), 128>>>(qh, ql, ch, cl);

    // 3) output projection (bf16x3) -> fp32 out
    gemm3_bf16<<<dim3(DIM / 128, MTOT / 128), 256, GEMM_SMEM>>>(
        ch, cl, woh, wol, out, MTOT, DIM, KD);
}

// round 11
// speedup vs baseline: 2.7713x; 2.7713x over previous
#include <cuda_runtime.h>
#include <cuda_bf16.h>
#include <cuda_fp16.h>
#include <math.h>
#include <float.h>
#include <stdint.h>

#define BATCH 2
#define SEQ   2048
#define DIM   1024
#define NH    16
#define DH    64
#define WIN   512
#define E3    3072
#define MTOT  (BATCH * SEQ)   // 4096
#define KD    1024

// ---------------- scratch (device globals; no allocation) ------------------
__device__ __half        g_xh[MTOT * KD],  g_xl[MTOT * KD];   // x fp16 hi/lo
__device__ __half        g_wq[E3 * KD];                        // Wqkv^T fp16
__device__ __half        g_wo[DIM * KD];                       // Wout^T fp16
__device__ __nv_bfloat16 g_qh[MTOT * E3],  g_ql[MTOT * E3];   // qkv bf16 hi/lo
__device__ __half        g_ch[MTOT * KD],  g_cl[MTOT * KD];   // ctx fp16 hi/lo

// ---------------- helpers ---------------------------------------------------
// bf16 pair split (used by GEMM1 epilogue + attention P fragments)
__device__ __forceinline__ uint32_t pack_bf16(float lo, float hi) {
    uint32_t r;
    asm("cvt.rn.bf16x2.f32 %0, %1, %2;" : "=r"(r) : "f"(hi), "f"(lo));
    return r;
}
__device__ __forceinline__ void split_bf16(float x, float y, uint32_t& hi, uint32_t& lo) {
    hi = pack_bf16(x, y);
    float xh = __uint_as_float(hi << 16);
    float yh = __uint_as_float(hi & 0xFFFF0000u);
    lo = pack_bf16(x - xh, y - yh);
}
// fp16 pair split (x prep + attention ctx epilogue)
__device__ __forceinline__ void split_f16(float x, float y, uint32_t& hi, uint32_t& lo) {
    __half2 h = __floats2half2_rn(x, y);
    hi = *(uint32_t*)&h;
    __half2 l = __floats2half2_rn(x - __low2float(h), y - __high2float(h));
    lo = *(uint32_t*)&l;
}
__device__ __forceinline__ void mma_bf16(float* c, const uint32_t* a, const uint32_t* b) {
    asm volatile(
        "mma.sync.aligned.m16n8k16.row.col.f32.bf16.bf16.f32 "
        "{%0,%1,%2,%3}, {%4,%5,%6,%7}, {%8,%9}, {%0,%1,%2,%3};"
        : "+f"(c[0]), "+f"(c[1]), "+f"(c[2]), "+f"(c[3])
        : "r"(a[0]), "r"(a[1]), "r"(a[2]), "r"(a[3]), "r"(b[0]), "r"(b[1]));
}
__device__ __forceinline__ void mma_f16(float* c, const uint32_t* a, const uint32_t* b) {
    asm volatile(
        "mma.sync.aligned.m16n8k16.row.col.f32.f16.f16.f32 "
        "{%0,%1,%2,%3}, {%4,%5,%6,%7}, {%8,%9}, {%0,%1,%2,%3};"
        : "+f"(c[0]), "+f"(c[1]), "+f"(c[2]), "+f"(c[3])
        : "r"(a[0]), "r"(a[1]), "r"(a[2]), "r"(a[3]), "r"(b[0]), "r"(b[1]));
}
__device__ __forceinline__ uint32_t smem_u32(const void* p) {
    return (uint32_t)__cvta_generic_to_shared(p);
}
#define CP16(s, g) \
    asm volatile("cp.async.cg.shared.global [%0], [%1], 16;" :: "r"(s), "l"(g))
#define CP_COMMIT() asm volatile("cp.async.commit_group;")
#define CP_WAIT(n)  asm volatile("cp.async.wait_group %0;" :: "n"(n))
#define LDSM4(r, a) \
    asm volatile("ldmatrix.sync.aligned.m8n8.x4.shared.b16 {%0,%1,%2,%3}, [%4];" \
        : "=r"((r)[0]), "=r"((r)[1]), "=r"((r)[2]), "=r"((r)[3]) : "r"(a))
#define LDSM4T(r, a) \
    asm volatile("ldmatrix.sync.aligned.m8n8.x4.trans.shared.b16 {%0,%1,%2,%3}, [%4];" \
        : "=r"((r)[0]), "=r"((r)[1]), "=r"((r)[2]), "=r"((r)[3]) : "r"(a))

// ---------------------------------------------------------------------------
// Prep kernels
// ---------------------------------------------------------------------------
__global__ __launch_bounds__(256) void split_x_kernel(
    const float* __restrict__ x, __half* __restrict__ xh, __half* __restrict__ xl)
{
    int i = blockIdx.x * 256 + threadIdx.x;
    float4 v = ((const float4*)x)[i];
    uint32_t h0, l0, h1, l1;
    split_f16(v.x, v.y, h0, l0);
    split_f16(v.z, v.w, h1, l1);
    ((uint2*)xh)[i] = make_uint2(h0, h1);
    ((uint2*)xl)[i] = make_uint2(l0, l1);
}

// W[K][N] fp32 -> Wt [N][K] fp16 (single precision-rounded copy)
__global__ __launch_bounds__(256) void tsplit_kernel(
    const float* __restrict__ W, __half* __restrict__ Wt, int N, int K)
{
    __shared__ float tile[32][33];
    int tx = threadIdx.x, ty = threadIdx.y;
    int n0 = blockIdx.x * 32, k0 = blockIdx.y * 32;
#pragma unroll
    for (int i = 0; i < 4; i++)
        tile[ty + 8 * i][tx] = W[(long)(k0 + ty + 8 * i) * N + n0 + tx];
    __syncthreads();
#pragma unroll
    for (int i = 0; i < 4; i++) {
        int n = ty + 8 * i;
        Wt[(long)(n0 + n) * K + k0 + tx] = __float2half_rn(tile[tx][n]);
    }
}

// ---------------------------------------------------------------------------
// fp16 2-pass GEMM: C = Ah*B + Al*B  (A hi/lo exact, B plain fp16, f32 acc).
// A*: [M][K] fp16 K-major. B: [N][K] fp16 K-major.
// Block tile 128x128, BK=32, 256 thr = 8 warps (2m x 4n of 64x32), 2 CTA/SM.
// MODE 0: fp32 C.  MODE 1: bf16 hi/lo C (cols < qcols scaled by 0.125).
// ---------------------------------------------------------------------------
#define LDT      40                           // fp16 per smem row (32 + 8 pad)
#define A_BYTES  (128 * LDT * 2)              // 10240
#define B_BYTES  (128 * LDT * 2)              // 10240
#define STG      (2 * A_BYTES + B_BYTES)      // 30720
#define GEMM_SMEM (2 * STG)                   // 61440

template <int MODE>
__global__ __launch_bounds__(256, 2) void gemm_2p(
    const __half* __restrict__ Ah, const __half* __restrict__ Al,
    const __half* __restrict__ Bp,
    float* __restrict__ Cf, __nv_bfloat16* __restrict__ Ch,
    __nv_bfloat16* __restrict__ Cl, int M, int N, int K, int qcols)
{
    extern __shared__ char smem[];
    const uint32_t sb = smem_u32(smem);
    const int tid = threadIdx.x, wid = tid >> 5, lane = tid & 31;
    const int wm = (wid & 1) * 64, wn = (wid >> 1) * 32;
    const long arow0 = (long)blockIdx.y * 128;
    const long brow0 = (long)blockIdx.x * 128;

    float acc[4][4][4] = {};

    const uint32_t a_off =
        (uint32_t)((wm + (lane & 7) + ((lane & 8) ? 8 : 0)) * (LDT * 2)
                   + ((lane & 16) ? 16 : 0));
    const uint32_t b_off = (uint32_t)(2 * A_BYTES
                   + (wn + (lane & 7) + ((lane & 16) ? 8 : 0)) * (LDT * 2)
                   + ((lane & 8) ? 16 : 0));

    const int nT = K / 32;

    auto issue = [&](int t) {
        const int s = t & 1, k0 = t * 32;
        const uint32_t st = sb + s * STG;
        // A hi/lo: 512 chunks each (128 rows x 4 chunks)
#pragma unroll
        for (int i = 0; i < 2; i++) {
            int idx = i * 256 + tid;
            int row = idx >> 2, kc = idx & 3;
            uint32_t so = st + row * (LDT * 2) + kc * 16;
            long go = (arow0 + row) * K + k0 + kc * 8;
            CP16(so, Ah + go);
            CP16(so + A_BYTES, Al + go);
        }
        // B: 512 chunks
#pragma unroll
        for (int i = 0; i < 2; i++) {
            int idx = i * 256 + tid;
            int row = idx >> 2, kc = idx & 3;
            uint32_t so = st + 2 * A_BYTES + row * (LDT * 2) + kc * 16;
            long go = (brow0 + row) * K + k0 + kc * 8;
            CP16(so, Bp + go);
        }
        CP_COMMIT();
    };

    issue(0);
    for (int t = 0; t < nT; t++) {
        if (t + 1 < nT) { issue(t + 1); CP_WAIT(1); }
        else            { CP_WAIT(0); }
        __syncthreads();

        const uint32_t st = sb + (t & 1) * STG;
#pragma unroll
        for (int ks = 0; ks < 2; ks++) {
            uint32_t ah[4][4], al[4][4], bh[4][2];
#pragma unroll
            for (int am = 0; am < 4; am++) {
                uint32_t a = st + a_off + am * (16 * LDT * 2) + ks * 32;
                LDSM4(ah[am], a);
                LDSM4(al[am], a + A_BYTES);
            }
#pragma unroll
            for (int g = 0; g < 2; g++) {
                uint32_t a = st + b_off + g * (16 * LDT * 2) + ks * 32;
                uint32_t r[4];
                LDSM4(r, a);
                bh[2*g][0] = r[0]; bh[2*g][1] = r[1];
                bh[2*g+1][0] = r[2]; bh[2*g+1][1] = r[3];
            }
            // pass 1: Al * B
#pragma unroll
            for (int am = 0; am < 4; am++)
#pragma unroll
                for (int bn = 0; bn < 4; bn++)
                    mma_f16(acc[am][bn], al[am], bh[bn]);
            // pass 2: Ah * B
#pragma unroll
            for (int am = 0; am < 4; am++)
#pragma unroll
                for (int bn = 0; bn < 4; bn++)
                    mma_f16(acc[am][bn], ah[am], bh[bn]);
        }
        __syncthreads();
    }

    // epilogue
#pragma unroll
    for (int am = 0; am < 4; am++)
#pragma unroll
        for (int bn = 0; bn < 4; bn++) {
            int row = blockIdx.y * 128 + wm + am * 16 + (lane >> 2);
            int col = blockIdx.x * 128 + wn + bn * 8 + 2 * (lane & 3);
            if (MODE == 0) {
                *(float2*)(Cf + (long)row * N + col) =
                    make_float2(acc[am][bn][0], acc[am][bn][1]);
                *(float2*)(Cf + (long)(row + 8) * N + col) =
                    make_float2(acc[am][bn][2], acc[am][bn][3]);
            } else {
                float scl = (col < qcols) ? 0.125f : 1.0f;
                uint32_t hh, ll;
                split_bf16(acc[am][bn][0] * scl, acc[am][bn][1] * scl, hh, ll);
                *(uint32_t*)(Ch + (long)row * N + col) = hh;
                *(uint32_t*)(Cl + (long)row * N + col) = ll;
                split_bf16(acc[am][bn][2] * scl, acc[am][bn][3] * scl, hh, ll);
                *(uint32_t*)(Ch + (long)(row + 8) * N + col) = hh;
                *(uint32_t*)(Cl + (long)(row + 8) * N + col) = ll;
            }
        }
}

// ---------------------------------------------------------------------------
// Sliding-window flash attention, bf16 hi/lo 3-pass on mma.sync (R7-proven).
// Inputs pre-split (Q pre-scaled). 128 q-rows/block, 4 warps, key tile 64.
// Epilogue writes ctx as fp16 hi/lo pairs for the fp16 output GEMM.
// ---------------------------------------------------------------------------
#define KVP 72   // bf16 per smem row (64 + 8 pad)

__global__ __launch_bounds__(128) void attn_mma(
    const __nv_bfloat16* __restrict__ qh, const __nv_bfloat16* __restrict__ ql,
    __half* __restrict__ ctxh, __half* __restrict__ ctxl)
{
    __shared__ __nv_bfloat16 Kh[64 * KVP], Kl[64 * KVP];
    __shared__ __nv_bfloat16 Vh[64 * KVP], Vl[64 * KVP];

    const int tid  = threadIdx.x;
    const int wid  = tid >> 5;
    const int lane = tid & 31;
    const int gid  = lane >> 2;
    const int tig  = lane & 3;
    const int i0   = blockIdx.x * 128;
    const int h    = blockIdx.y;
    const int b    = blockIdx.z;

    const long rowb = (long)b * SEQ;
    const int qcol = h * DH;
    const int kcol = DIM + h * DH;
    const int vcol = 2 * DIM + h * DH;

    uint32_t qfh[2][4][4], qfl[2][4][4];
#pragma unroll
    for (int am = 0; am < 2; am++) {
        long r = rowb + i0 + wid * 32 + am * 16 + gid;
#pragma unroll
        for (int s = 0; s < 4; s++) {
            int c = qcol + s * 16 + 2 * tig;
            qfh[am][s][0] = *(const uint32_t*)(qh + r * E3 + c);
            qfh[am][s][1] = *(const uint32_t*)(qh + (r + 8) * E3 + c);
            qfh[am][s][2] = *(const uint32_t*)(qh + r * E3 + c + 8);
            qfh[am][s][3] = *(const uint32_t*)(qh + (r + 8) * E3 + c + 8);
            qfl[am][s][0] = *(const uint32_t*)(ql + r * E3 + c);
            qfl[am][s][1] = *(const uint32_t*)(ql + (r + 8) * E3 + c);
            qfl[am][s][2] = *(const uint32_t*)(ql + r * E3 + c + 8);
            qfl[am][s][3] = *(const uint32_t*)(ql + (r + 8) * E3 + c + 8);
        }
    }

    const uint32_t kh_b = smem_u32(Kh), kl_b = smem_u32(Kl);
    const uint32_t vh_b = smem_u32(Vh), vl_b = smem_u32(Vl);
    const uint32_t koff = (uint32_t)(((lane & 7) + ((lane & 16) ? 8 : 0)) * (KVP * 2)
                                     + ((lane & 8) ? 16 : 0));
    const uint32_t voff = (uint32_t)(((lane & 7) + ((lane & 8) ? 8 : 0)) * (KVP * 2)
                                     + ((lane & 16) ? 16 : 0));

    float mrow[2][2], lrow[2][2], o[2][8][4] = {};
#pragma unroll
    for (int am = 0; am < 2; am++) {
        mrow[am][0] = -FLT_MAX; mrow[am][1] = -FLT_MAX;
        lrow[am][0] = 0.f;      lrow[am][1] = 0.f;
    }

    int t0 = (i0 - WIN + 1) >> 6; if (t0 < 0) t0 = 0;
    const int t1 = (i0 + 127) >> 6;

    for (int t = t0; t <= t1; t++) {
        const int kt0 = t << 6;
        __syncthreads();

#pragma unroll
        for (int i = 0; i < 4; i++) {
            int idx = i * 128 + tid;
            int row = idx >> 3, ch = idx & 7;
            long gro = (rowb + kt0 + row) * E3;
            uint32_t so = row * (KVP * 2) + ch * 16;
            CP16(kh_b + so, qh + gro + kcol + ch * 8);
            CP16(kl_b + so, ql + gro + kcol + ch * 8);
            CP16(vh_b + so, qh + gro + vcol + ch * 8);
            CP16(vl_b + so, ql + gro + vcol + ch * 8);
        }
        CP_COMMIT();
        CP_WAIT(0);
        __syncthreads();

        float s[2][8][4] = {};
#pragma unroll
        for (int ks = 0; ks < 4; ks++) {
            uint32_t kh[8][2], kl[8][2];
#pragma unroll
            for (int g = 0; g < 4; g++) {
                uint32_t a = koff + g * (16 * KVP * 2) + ks * 32;
                uint32_t r[4];
                LDSM4(r, kh_b + a);
                kh[2*g][0] = r[0]; kh[2*g][1] = r[1];
                kh[2*g+1][0] = r[2]; kh[2*g+1][1] = r[3];
                LDSM4(r, kl_b + a);
                kl[2*g][0] = r[0]; kl[2*g][1] = r[1];
                kl[2*g+1][0] = r[2]; kl[2*g+1][1] = r[3];
            }
#pragma unroll
            for (int bn = 0; bn < 8; bn++)
#pragma unroll
                for (int am = 0; am < 2; am++)
                    mma_bf16(s[am][bn], qfl[am][ks], kh[bn]);
#pragma unroll
            for (int bn = 0; bn < 8; bn++)
#pragma unroll
                for (int am = 0; am < 2; am++)
                    mma_bf16(s[am][bn], qfh[am][ks], kl[bn]);
#pragma unroll
            for (int bn = 0; bn < 8; bn++)
#pragma unroll
                for (int am = 0; am < 2; am++)
                    mma_bf16(s[am][bn], qfh[am][ks], kh[bn]);
        }

#pragma unroll
        for (int am = 0; am < 2; am++) {
            int qi0 = i0 + wid * 32 + am * 16 + gid;
            int qi1 = qi0 + 8;
#pragma unroll
            for (int bn = 0; bn < 8; bn++) {
                int c0 = kt0 + bn * 8 + 2 * tig, c1 = c0 + 1;
                if (c0 > qi0 || c0 < qi0 - (WIN - 1)) s[am][bn][0] = -FLT_MAX;
                if (c1 > qi0 || c1 < qi0 - (WIN - 1)) s[am][bn][1] = -FLT_MAX;
                if (c0 > qi1 || c0 < qi1 - (WIN - 1)) s[am][bn][2] = -FLT_MAX;
                if (c1 > qi1 || c1 < qi1 - (WIN - 1)) s[am][bn][3] = -FLT_MAX;
            }
            float mx0 = -FLT_MAX, mx1 = -FLT_MAX;
#pragma unroll
            for (int bn = 0; bn < 8; bn++) {
                mx0 = fmaxf(mx0, fmaxf(s[am][bn][0], s[am][bn][1]));
                mx1 = fmaxf(mx1, fmaxf(s[am][bn][2], s[am][bn][3]));
            }
            mx0 = fmaxf(mx0, __shfl_xor_sync(0xffffffffu, mx0, 1));
            mx0 = fmaxf(mx0, __shfl_xor_sync(0xffffffffu, mx0, 2));
            mx1 = fmaxf(mx1, __shfl_xor_sync(0xffffffffu, mx1, 1));
            mx1 = fmaxf(mx1, __shfl_xor_sync(0xffffffffu, mx1, 2));
            float mn0 = fmaxf(mrow[am][0], mx0);
            float mn1 = fmaxf(mrow[am][1], mx1);
            float a0 = __expf(mrow[am][0] - mn0);
            float a1 = __expf(mrow[am][1] - mn1);
            mrow[am][0] = mn0; mrow[am][1] = mn1;
            float rs0 = 0.f, rs1 = 0.f;
#pragma unroll
            for (int bn = 0; bn < 8; bn++) {
                s[am][bn][0] = __expf(s[am][bn][0] - mn0);
                s[am][bn][1] = __expf(s[am][bn][1] - mn0);
                s[am][bn][2] = __expf(s[am][bn][2] - mn1);
                s[am][bn][3] = __expf(s[am][bn][3] - mn1);
                rs0 += s[am][bn][0] + s[am][bn][1];
                rs1 += s[am][bn][2] + s[am][bn][3];
            }
            rs0 += __shfl_xor_sync(0xffffffffu, rs0, 1);
            rs0 += __shfl_xor_sync(0xffffffffu, rs0, 2);
            rs1 += __shfl_xor_sync(0xffffffffu, rs1, 1);
            rs1 += __shfl_xor_sync(0xffffffffu, rs1, 2);
            lrow[am][0] = lrow[am][0] * a0 + rs0;
            lrow[am][1] = lrow[am][1] * a1 + rs1;
#pragma unroll
            for (int bn = 0; bn < 8; bn++) {
                o[am][bn][0] *= a0; o[am][bn][1] *= a0;
                o[am][bn][2] *= a1; o[am][bn][3] *= a1;
            }
        }

        uint32_t pf[2][4][4], pg[2][4][4];
#pragma unroll
        for (int am = 0; am < 2; am++)
#pragma unroll
            for (int kk = 0; kk < 4; kk++) {
                split_bf16(s[am][2*kk][0],   s[am][2*kk][1],   pf[am][kk][0], pg[am][kk][0]);
                split_bf16(s[am][2*kk][2],   s[am][2*kk][3],   pf[am][kk][1], pg[am][kk][1]);
                split_bf16(s[am][2*kk+1][0], s[am][2*kk+1][1], pf[am][kk][2], pg[am][kk][2]);
                split_bf16(s[am][2*kk+1][2], s[am][2*kk+1][3], pf[am][kk][3], pg[am][kk][3]);
            }

#pragma unroll
        for (int kk = 0; kk < 4; kk++) {
            uint32_t vh[8][2], vl[8][2];
#pragma unroll
            for (int g = 0; g < 4; g++) {
                uint32_t a = voff + kk * (16 * KVP * 2) + g * 32;
                uint32_t r[4];
                LDSM4T(r, vh_b + a);
                vh[2*g][0] = r[0]; vh[2*g][1] = r[1];
                vh[2*g+1][0] = r[2]; vh[2*g+1][1] = r[3];
                LDSM4T(r, vl_b + a);
                vl[2*g][0] = r[0]; vl[2*g][1] = r[1];
                vl[2*g+1][0] = r[2]; vl[2*g+1][1] = r[3];
            }
#pragma unroll
            for (int bn = 0; bn < 8; bn++)
#pragma unroll
                for (int am = 0; am < 2; am++)
                    mma_bf16(o[am][bn], pg[am][kk], vh[bn]);
#pragma unroll
            for (int bn = 0; bn < 8; bn++)
#pragma unroll
                for (int am = 0; am < 2; am++)
                    mma_bf16(o[am][bn], pf[am][kk], vl[bn]);
#pragma unroll
            for (int bn = 0; bn < 8; bn++)
#pragma unroll
                for (int am = 0; am < 2; am++)
                    mma_bf16(o[am][bn], pf[am][kk], vh[bn]);
        }
    }

    // ---- epilogue: normalize, split to fp16 hi/lo ctx
#pragma unroll
    for (int am = 0; am < 2; am++) {
        float inv0 = 1.f / lrow[am][0];
        float inv1 = 1.f / lrow[am][1];
        long r0 = rowb + i0 + wid * 32 + am * 16 + gid;
#pragma unroll
        for (int bn = 0; bn < 8; bn++) {
            int col = h * DH + bn * 8 + 2 * tig;
            uint32_t hh, ll;
            split_f16(o[am][bn][0] * inv0, o[am][bn][1] * inv0, hh, ll);
            *(uint32_t*)(ctxh + r0 * DIM + col) = hh;
            *(uint32_t*)(ctxl + r0 * DIM + col) = ll;
            split_f16(o[am][bn][2] * inv1, o[am][bn][3] * inv1, hh, ll);
            *(uint32_t*)(ctxh + (r0 + 8) * DIM + col) = hh;
            *(uint32_t*)(ctxl + (r0 + 8) * DIM + col) = ll;
        }
    }
}

// ---------------------------------------------------------------------------
extern "C" void kernel_launch(void* const* d_in, const int* in_sizes, int n_in,
                              void* d_out, int out_size)
{
    (void)in_sizes; (void)n_in; (void)out_size;
    const float* x    = (const float*)d_in[0];
    const float* Wqkv = (const float*)d_in[1];
    const float* Wout = (const float*)d_in[2];
    float* out = (float*)d_out;

    __half *xh, *xl, *wq, *wo, *ch, *cl;
    __nv_bfloat16 *qh, *ql;
    cudaGetSymbolAddress((void**)&xh, g_xh);
    cudaGetSymbolAddress((void**)&xl, g_xl);
    cudaGetSymbolAddress((void**)&wq, g_wq);
    cudaGetSymbolAddress((void**)&wo, g_wo);
    cudaGetSymbolAddress((void**)&qh, g_qh);
    cudaGetSymbolAddress((void**)&ql, g_ql);
    cudaGetSymbolAddress((void**)&ch, g_ch);
    cudaGetSymbolAddress((void**)&cl, g_cl);

    cudaFuncSetAttribute(gemm_2p<0>,
                         cudaFuncAttributeMaxDynamicSharedMemorySize, GEMM_SMEM);
    cudaFuncSetAttribute(gemm_2p<1>,
                         cudaFuncAttributeMaxDynamicSharedMemorySize, GEMM_SMEM);

    // prep
    split_x_kernel<<<(MTOT * KD) / 1024, 256>>>(x, xh, xl);
    tsplit_kernel<<<dim3(E3 / 32, KD / 32), dim3(32, 8)>>>(Wqkv, wq, E3, KD);
    tsplit_kernel<<<dim3(DIM / 32, KD / 32), dim3(32, 8)>>>(Wout, wo, DIM, KD);

    // 1) QKV projection (fp16 2-pass) -> bf16 hi/lo qkv (Q cols pre-scaled)
    gemm_2p<1><<<dim3(E3 / 128, MTOT / 128), 256, GEMM_SMEM>>>(
        xh, xl, wq, nullptr, qh, ql, MTOT, E3, KD, DIM);

    // 2) sliding-window attention (bf16x3) -> fp16 hi/lo ctx
    attn_mma<<<dim3(SEQ / 128, NH, BATCH), 128>>>(qh, ql, ch, cl);

    // 3) output projection (fp16 2-pass) -> fp32 out
    gemm_2p<0><<<dim3(DIM / 128, MTOT / 128), 256, GEMM_SMEM>>>(
        ch, cl, wo, out, nullptr, nullptr, MTOT, DIM, KD, 0);
}

// round 12
// speedup vs baseline: 3.0645x; 1.1058x over previous
#include <cuda_runtime.h>
#include <cuda_fp16.h>
#include <math.h>
#include <float.h>
#include <stdint.h>

#define BATCH 2
#define SEQ   2048
#define DIM   1024
#define NH    16
#define DH    64
#define WIN   512
#define E3    3072
#define MTOT  (BATCH * SEQ)   // 4096
#define KD    1024

// ---------------- scratch (device globals; no allocation) ------------------
__device__ __half g_xh[MTOT * KD],  g_xl[MTOT * KD];   // x fp16 hi/lo
__device__ __half g_wq[E3 * KD];                        // Wqkv^T fp16
__device__ __half g_wo[DIM * KD];                       // Wout^T fp16
__device__ __half g_qh[MTOT * E3],  g_ql[MTOT * E3];   // qkv: Q hi/lo, K/V plain in g_qh
__device__ __half g_ch[MTOT * KD],  g_cl[MTOT * KD];   // ctx fp16 hi/lo

// ---------------- helpers ---------------------------------------------------
__device__ __forceinline__ void split_f16(float x, float y, uint32_t& hi, uint32_t& lo) {
    __half2 h = __floats2half2_rn(x, y);
    hi = *(uint32_t*)&h;
    __half2 l = __floats2half2_rn(x - __low2float(h), y - __high2float(h));
    lo = *(uint32_t*)&l;
}
__device__ __forceinline__ void mma_f16(float* c, const uint32_t* a, const uint32_t* b) {
    asm volatile(
        "mma.sync.aligned.m16n8k16.row.col.f32.f16.f16.f32 "
        "{%0,%1,%2,%3}, {%4,%5,%6,%7}, {%8,%9}, {%0,%1,%2,%3};"
        : "+f"(c[0]), "+f"(c[1]), "+f"(c[2]), "+f"(c[3])
        : "r"(a[0]), "r"(a[1]), "r"(a[2]), "r"(a[3]), "r"(b[0]), "r"(b[1]));
}
__device__ __forceinline__ uint32_t smem_u32(const void* p) {
    return (uint32_t)__cvta_generic_to_shared(p);
}
#define CP16(s, g) \
    asm volatile("cp.async.cg.shared.global [%0], [%1], 16;" :: "r"(s), "l"(g))
#define CP_COMMIT() asm volatile("cp.async.commit_group;")
#define CP_WAIT(n)  asm volatile("cp.async.wait_group %0;" :: "n"(n))
#define LDSM4(r, a) \
    asm volatile("ldmatrix.sync.aligned.m8n8.x4.shared.b16 {%0,%1,%2,%3}, [%4];" \
        : "=r"((r)[0]), "=r"((r)[1]), "=r"((r)[2]), "=r"((r)[3]) : "r"(a))
#define LDSM4T(r, a) \
    asm volatile("ldmatrix.sync.aligned.m8n8.x4.trans.shared.b16 {%0,%1,%2,%3}, [%4];" \
        : "=r"((r)[0]), "=r"((r)[1]), "=r"((r)[2]), "=r"((r)[3]) : "r"(a))

// ---------------------------------------------------------------------------
// Prep kernels
// ---------------------------------------------------------------------------
__global__ __launch_bounds__(256) void split_x_kernel(
    const float* __restrict__ x, __half* __restrict__ xh, __half* __restrict__ xl)
{
    int i = blockIdx.x * 256 + threadIdx.x;
    float4 v = ((const float4*)x)[i];
    uint32_t h0, l0, h1, l1;
    split_f16(v.x, v.y, h0, l0);
    split_f16(v.z, v.w, h1, l1);
    ((uint2*)xh)[i] = make_uint2(h0, h1);
    ((uint2*)xl)[i] = make_uint2(l0, l1);
}

// W[K][N] fp32 -> Wt [N][K] fp16
__global__ __launch_bounds__(256) void tsplit_kernel(
    const float* __restrict__ W, __half* __restrict__ Wt, int N, int K)
{
    __shared__ float tile[32][33];
    int tx = threadIdx.x, ty = threadIdx.y;
    int n0 = blockIdx.x * 32, k0 = blockIdx.y * 32;
#pragma unroll
    for (int i = 0; i < 4; i++)
        tile[ty + 8 * i][tx] = W[(long)(k0 + ty + 8 * i) * N + n0 + tx];
    __syncthreads();
#pragma unroll
    for (int i = 0; i < 4; i++) {
        int n = ty + 8 * i;
        Wt[(long)(n0 + n) * K + k0 + tx] = __float2half_rn(tile[tx][n]);
    }
}

// ---------------------------------------------------------------------------
// fp16 2-pass GEMM: C = Ah*B + Al*B  (A hi/lo exact, B plain fp16, f32 acc).
// A*: [M][K] fp16 K-major. B: [N][K] fp16 K-major.
// Block tile 128x128, BK=32, 256 thr = 8 warps (2m x 4n of 64x32), 2 CTA/SM.
// MODE 0: fp32 C.
// MODE 1: qkv layout — cols < qcols: fp16 hi/lo scaled 0.125 (Q);
//         cols >= qcols: plain fp16 into Ch only (K/V).
// ---------------------------------------------------------------------------
#define LDT      40                           // fp16 per smem row (32 + 8 pad)
#define A_BYTES  (128 * LDT * 2)              // 10240
#define B_BYTES  (128 * LDT * 2)              // 10240
#define STG      (2 * A_BYTES + B_BYTES)      // 30720
#define GEMM_SMEM (2 * STG)                   // 61440

template <int MODE>
__global__ __launch_bounds__(256, 2) void gemm_2p(
    const __half* __restrict__ Ah, const __half* __restrict__ Al,
    const __half* __restrict__ Bp,
    float* __restrict__ Cf, __half* __restrict__ Ch,
    __half* __restrict__ Cl, int M, int N, int K, int qcols)
{
    extern __shared__ char smem[];
    const uint32_t sb = smem_u32(smem);
    const int tid = threadIdx.x, wid = tid >> 5, lane = tid & 31;
    const int wm = (wid & 1) * 64, wn = (wid >> 1) * 32;
    const long arow0 = (long)blockIdx.y * 128;
    const long brow0 = (long)blockIdx.x * 128;

    float acc[4][4][4] = {};

    const uint32_t a_off =
        (uint32_t)((wm + (lane & 7) + ((lane & 8) ? 8 : 0)) * (LDT * 2)
                   + ((lane & 16) ? 16 : 0));
    const uint32_t b_off = (uint32_t)(2 * A_BYTES
                   + (wn + (lane & 7) + ((lane & 16) ? 8 : 0)) * (LDT * 2)
                   + ((lane & 8) ? 16 : 0));

    const int nT = K / 32;

    auto issue = [&](int t) {
        const int s = t & 1, k0 = t * 32;
        const uint32_t st = sb + s * STG;
#pragma unroll
        for (int i = 0; i < 2; i++) {
            int idx = i * 256 + tid;
            int row = idx >> 2, kc = idx & 3;
            uint32_t so = st + row * (LDT * 2) + kc * 16;
            long go = (arow0 + row) * K + k0 + kc * 8;
            CP16(so, Ah + go);
            CP16(so + A_BYTES, Al + go);
        }
#pragma unroll
        for (int i = 0; i < 2; i++) {
            int idx = i * 256 + tid;
            int row = idx >> 2, kc = idx & 3;
            uint32_t so = st + 2 * A_BYTES + row * (LDT * 2) + kc * 16;
            long go = (brow0 + row) * K + k0 + kc * 8;
            CP16(so, Bp + go);
        }
        CP_COMMIT();
    };

    issue(0);
    for (int t = 0; t < nT; t++) {
        if (t + 1 < nT) { issue(t + 1); CP_WAIT(1); }
        else            { CP_WAIT(0); }
        __syncthreads();

        const uint32_t st = sb + (t & 1) * STG;
#pragma unroll
        for (int ks = 0; ks < 2; ks++) {
            uint32_t ah[4][4], al[4][4], bh[4][2];
#pragma unroll
            for (int am = 0; am < 4; am++) {
                uint32_t a = st + a_off + am * (16 * LDT * 2) + ks * 32;
                LDSM4(ah[am], a);
                LDSM4(al[am], a + A_BYTES);
            }
#pragma unroll
            for (int g = 0; g < 2; g++) {
                uint32_t a = st + b_off + g * (16 * LDT * 2) + ks * 32;
                uint32_t r[4];
                LDSM4(r, a);
                bh[2*g][0] = r[0]; bh[2*g][1] = r[1];
                bh[2*g+1][0] = r[2]; bh[2*g+1][1] = r[3];
            }
#pragma unroll
            for (int am = 0; am < 4; am++)
#pragma unroll
                for (int bn = 0; bn < 4; bn++)
                    mma_f16(acc[am][bn], al[am], bh[bn]);
#pragma unroll
            for (int am = 0; am < 4; am++)
#pragma unroll
                for (int bn = 0; bn < 4; bn++)
                    mma_f16(acc[am][bn], ah[am], bh[bn]);
        }
        __syncthreads();
    }

    // epilogue
#pragma unroll
    for (int am = 0; am < 4; am++)
#pragma unroll
        for (int bn = 0; bn < 4; bn++) {
            int row = blockIdx.y * 128 + wm + am * 16 + (lane >> 2);
            int col = blockIdx.x * 128 + wn + bn * 8 + 2 * (lane & 3);
            if (MODE == 0) {
                *(float2*)(Cf + (long)row * N + col) =
                    make_float2(acc[am][bn][0], acc[am][bn][1]);
                *(float2*)(Cf + (long)(row + 8) * N + col) =
                    make_float2(acc[am][bn][2], acc[am][bn][3]);
            } else {
                if (col < qcols) {
                    // Q: scale + fp16 hi/lo split
                    uint32_t hh, ll;
                    split_f16(acc[am][bn][0] * 0.125f, acc[am][bn][1] * 0.125f, hh, ll);
                    *(uint32_t*)(Ch + (long)row * N + col) = hh;
                    *(uint32_t*)(Cl + (long)row * N + col) = ll;
                    split_f16(acc[am][bn][2] * 0.125f, acc[am][bn][3] * 0.125f, hh, ll);
                    *(uint32_t*)(Ch + (long)(row + 8) * N + col) = hh;
                    *(uint32_t*)(Cl + (long)(row + 8) * N + col) = ll;
                } else {
                    // K / V: plain fp16 (Ch only)
                    __half2 p0 = __floats2half2_rn(acc[am][bn][0], acc[am][bn][1]);
                    __half2 p1 = __floats2half2_rn(acc[am][bn][2], acc[am][bn][3]);
                    *(__half2*)(Ch + (long)row * N + col) = p0;
                    *(__half2*)(Ch + (long)(row + 8) * N + col) = p1;
                }
            }
        }
}

// ---------------------------------------------------------------------------
// Sliding-window flash attention, fp16 2-pass:
//   S = (Qh + Ql) * K   (K plain fp16)
//   O = (Ph + Pl) * V   (V plain fp16)
// 128 q-rows/block, 4 warps, key tile 64. Epilogue -> fp16 hi/lo ctx.
// ---------------------------------------------------------------------------
#define KVP 72   // fp16 per smem row (64 + 8 pad)

__global__ __launch_bounds__(128) void attn_mma(
    const __half* __restrict__ qh, const __half* __restrict__ ql,
    __half* __restrict__ ctxh, __half* __restrict__ ctxl)
{
    __shared__ __half Ks[64 * KVP];
    __shared__ __half Vs[64 * KVP];

    const int tid  = threadIdx.x;
    const int wid  = tid >> 5;
    const int lane = tid & 31;
    const int gid  = lane >> 2;
    const int tig  = lane & 3;
    const int i0   = blockIdx.x * 128;
    const int h    = blockIdx.y;
    const int b    = blockIdx.z;

    const long rowb = (long)b * SEQ;
    const int qcol = h * DH;
    const int kcol = DIM + h * DH;
    const int vcol = 2 * DIM + h * DH;

    // Q fragments (pre-scaled fp16 hi/lo from GEMM1 epilogue)
    uint32_t qfh[2][4][4], qfl[2][4][4];
#pragma unroll
    for (int am = 0; am < 2; am++) {
        long r = rowb + i0 + wid * 32 + am * 16 + gid;
#pragma unroll
        for (int s = 0; s < 4; s++) {
            int c = qcol + s * 16 + 2 * tig;
            qfh[am][s][0] = *(const uint32_t*)(qh + r * E3 + c);
            qfh[am][s][1] = *(const uint32_t*)(qh + (r + 8) * E3 + c);
            qfh[am][s][2] = *(const uint32_t*)(qh + r * E3 + c + 8);
            qfh[am][s][3] = *(const uint32_t*)(qh + (r + 8) * E3 + c + 8);
            qfl[am][s][0] = *(const uint32_t*)(ql + r * E3 + c);
            qfl[am][s][1] = *(const uint32_t*)(ql + (r + 8) * E3 + c);
            qfl[am][s][2] = *(const uint32_t*)(ql + r * E3 + c + 8);
            qfl[am][s][3] = *(const uint32_t*)(ql + (r + 8) * E3 + c + 8);
        }
    }

    const uint32_t ks_b = smem_u32(Ks), vs_b = smem_u32(Vs);
    const uint32_t koff = (uint32_t)(((lane & 7) + ((lane & 16) ? 8 : 0)) * (KVP * 2)
                                     + ((lane & 8) ? 16 : 0));
    const uint32_t voff = (uint32_t)(((lane & 7) + ((lane & 8) ? 8 : 0)) * (KVP * 2)
                                     + ((lane & 16) ? 16 : 0));

    float mrow[2][2], lrow[2][2], o[2][8][4] = {};
#pragma unroll
    for (int am = 0; am < 2; am++) {
        mrow[am][0] = -FLT_MAX; mrow[am][1] = -FLT_MAX;
        lrow[am][0] = 0.f;      lrow[am][1] = 0.f;
    }

    int t0 = (i0 - WIN + 1) >> 6; if (t0 < 0) t0 = 0;
    const int t1 = (i0 + 127) >> 6;

    for (int t = t0; t <= t1; t++) {
        const int kt0 = t << 6;
        __syncthreads();

        // cp.async K/V plain fp16 tiles (64 x 64 each)
#pragma unroll
        for (int i = 0; i < 4; i++) {
            int idx = i * 128 + tid;
            int row = idx >> 3, ch = idx & 7;
            long gro = (rowb + kt0 + row) * E3;
            uint32_t so = row * (KVP * 2) + ch * 16;
            CP16(ks_b + so, qh + gro + kcol + ch * 8);
            CP16(vs_b + so, qh + gro + vcol + ch * 8);
        }
        CP_COMMIT();
        CP_WAIT(0);
        __syncthreads();

        // ---- S = (Qh + Ql) K^T  (2 passes)
        float s[2][8][4] = {};
#pragma unroll
        for (int ks = 0; ks < 4; ks++) {
            uint32_t kf[8][2];
#pragma unroll
            for (int g = 0; g < 4; g++) {
                uint32_t a = koff + g * (16 * KVP * 2) + ks * 32;
                uint32_t r[4];
                LDSM4(r, ks_b + a);
                kf[2*g][0] = r[0]; kf[2*g][1] = r[1];
                kf[2*g+1][0] = r[2]; kf[2*g+1][1] = r[3];
            }
#pragma unroll
            for (int bn = 0; bn < 8; bn++)
#pragma unroll
                for (int am = 0; am < 2; am++)
                    mma_f16(s[am][bn], qfl[am][ks], kf[bn]);
#pragma unroll
            for (int bn = 0; bn < 8; bn++)
#pragma unroll
                for (int am = 0; am < 2; am++)
                    mma_f16(s[am][bn], qfh[am][ks], kf[bn]);
        }

        // ---- mask + online softmax
#pragma unroll
        for (int am = 0; am < 2; am++) {
            int qi0 = i0 + wid * 32 + am * 16 + gid;
            int qi1 = qi0 + 8;
#pragma unroll
            for (int bn = 0; bn < 8; bn++) {
                int c0 = kt0 + bn * 8 + 2 * tig, c1 = c0 + 1;
                if (c0 > qi0 || c0 < qi0 - (WIN - 1)) s[am][bn][0] = -FLT_MAX;
                if (c1 > qi0 || c1 < qi0 - (WIN - 1)) s[am][bn][1] = -FLT_MAX;
                if (c0 > qi1 || c0 < qi1 - (WIN - 1)) s[am][bn][2] = -FLT_MAX;
                if (c1 > qi1 || c1 < qi1 - (WIN - 1)) s[am][bn][3] = -FLT_MAX;
            }
            float mx0 = -FLT_MAX, mx1 = -FLT_MAX;
#pragma unroll
            for (int bn = 0; bn < 8; bn++) {
                mx0 = fmaxf(mx0, fmaxf(s[am][bn][0], s[am][bn][1]));
                mx1 = fmaxf(mx1, fmaxf(s[am][bn][2], s[am][bn][3]));
            }
            mx0 = fmaxf(mx0, __shfl_xor_sync(0xffffffffu, mx0, 1));
            mx0 = fmaxf(mx0, __shfl_xor_sync(0xffffffffu, mx0, 2));
            mx1 = fmaxf(mx1, __shfl_xor_sync(0xffffffffu, mx1, 1));
            mx1 = fmaxf(mx1, __shfl_xor_sync(0xffffffffu, mx1, 2));
            float mn0 = fmaxf(mrow[am][0], mx0);
            float mn1 = fmaxf(mrow[am][1], mx1);
            float a0 = __expf(mrow[am][0] - mn0);
            float a1 = __expf(mrow[am][1] - mn1);
            mrow[am][0] = mn0; mrow[am][1] = mn1;
            float rs0 = 0.f, rs1 = 0.f;
#pragma unroll
            for (int bn = 0; bn < 8; bn++) {
                s[am][bn][0] = __expf(s[am][bn][0] - mn0);
                s[am][bn][1] = __expf(s[am][bn][1] - mn0);
                s[am][bn][2] = __expf(s[am][bn][2] - mn1);
                s[am][bn][3] = __expf(s[am][bn][3] - mn1);
                rs0 += s[am][bn][0] + s[am][bn][1];
                rs1 += s[am][bn][2] + s[am][bn][3];
            }
            rs0 += __shfl_xor_sync(0xffffffffu, rs0, 1);
            rs0 += __shfl_xor_sync(0xffffffffu, rs0, 2);
            rs1 += __shfl_xor_sync(0xffffffffu, rs1, 1);
            rs1 += __shfl_xor_sync(0xffffffffu, rs1, 2);
            lrow[am][0] = lrow[am][0] * a0 + rs0;
            lrow[am][1] = lrow[am][1] * a1 + rs1;
#pragma unroll
            for (int bn = 0; bn < 8; bn++) {
                o[am][bn][0] *= a0; o[am][bn][1] *= a0;
                o[am][bn][2] *= a1; o[am][bn][3] *= a1;
            }
        }

        // ---- P fragments (fp16 hi/lo, exact-ish) from S accumulators
        uint32_t pf[2][4][4], pg[2][4][4];
#pragma unroll
        for (int am = 0; am < 2; am++)
#pragma unroll
            for (int kk = 0; kk < 4; kk++) {
                split_f16(s[am][2*kk][0],   s[am][2*kk][1],   pf[am][kk][0], pg[am][kk][0]);
                split_f16(s[am][2*kk][2],   s[am][2*kk][3],   pf[am][kk][1], pg[am][kk][1]);
                split_f16(s[am][2*kk+1][0], s[am][2*kk+1][1], pf[am][kk][2], pg[am][kk][2]);
                split_f16(s[am][2*kk+1][2], s[am][2*kk+1][3], pf[am][kk][3], pg[am][kk][3]);
            }

        // ---- O += (Ph + Pl) V  (2 passes)
#pragma unroll
        for (int kk = 0; kk < 4; kk++) {
            uint32_t vf[8][2];
#pragma unroll
            for (int g = 0; g < 4; g++) {
                uint32_t a = voff + kk * (16 * KVP * 2) + g * 32;
                uint32_t r[4];
                LDSM4T(r, vs_b + a);
                vf[2*g][0] = r[0]; vf[2*g][1] = r[1];
                vf[2*g+1][0] = r[2]; vf[2*g+1][1] = r[3];
            }
#pragma unroll
            for (int bn = 0; bn < 8; bn++)
#pragma unroll
                for (int am = 0; am < 2; am++)
                    mma_f16(o[am][bn], pg[am][kk], vf[bn]);
#pragma unroll
            for (int bn = 0; bn < 8; bn++)
#pragma unroll
                for (int am = 0; am < 2; am++)
                    mma_f16(o[am][bn], pf[am][kk], vf[bn]);
        }
    }

    // ---- epilogue: normalize, split to fp16 hi/lo ctx
#pragma unroll
    for (int am = 0; am < 2; am++) {
        float inv0 = 1.f / lrow[am][0];
        float inv1 = 1.f / lrow[am][1];
        long r0 = rowb + i0 + wid * 32 + am * 16 + gid;
#pragma unroll
        for (int bn = 0; bn < 8; bn++) {
            int col = h * DH + bn * 8 + 2 * tig;
            uint32_t hh, ll;
            split_f16(o[am][bn][0] * inv0, o[am][bn][1] * inv0, hh, ll);
            *(uint32_t*)(ctxh + r0 * DIM + col) = hh;
            *(uint32_t*)(ctxl + r0 * DIM + col) = ll;
            split_f16(o[am][bn][2] * inv1, o[am][bn][3] * inv1, hh, ll);
            *(uint32_t*)(ctxh + (r0 + 8) * DIM + col) = hh;
            *(uint32_t*)(ctxl + (r0 + 8) * DIM + col) = ll;
        }
    }
}

// ---------------------------------------------------------------------------
extern "C" void kernel_launch(void* const* d_in, const int* in_sizes, int n_in,
                              void* d_out, int out_size)
{
    (void)in_sizes; (void)n_in; (void)out_size;
    const float* x    = (const float*)d_in[0];
    const float* Wqkv = (const float*)d_in[1];
    const float* Wout = (const float*)d_in[2];
    float* out = (float*)d_out;

    __half *xh, *xl, *wq, *wo, *qh, *ql, *ch, *cl;
    cudaGetSymbolAddress((void**)&xh, g_xh);
    cudaGetSymbolAddress((void**)&xl, g_xl);
    cudaGetSymbolAddress((void**)&wq, g_wq);
    cudaGetSymbolAddress((void**)&wo, g_wo);
    cudaGetSymbolAddress((void**)&qh, g_qh);
    cudaGetSymbolAddress((void**)&ql, g_ql);
    cudaGetSymbolAddress((void**)&ch, g_ch);
    cudaGetSymbolAddress((void**)&cl, g_cl);

    cudaFuncSetAttribute(gemm_2p<0>,
                         cudaFuncAttributeMaxDynamicSharedMemorySize, GEMM_SMEM);
    cudaFuncSetAttribute(gemm_2p<1>,
                         cudaFuncAttributeMaxDynamicSharedMemorySize, GEMM_SMEM);

    // prep
    split_x_kernel<<<(MTOT * KD) / 1024, 256>>>(x, xh, xl);
    tsplit_kernel<<<dim3(E3 / 32, KD / 32), dim3(32, 8)>>>(Wqkv, wq, E3, KD);
    tsplit_kernel<<<dim3(DIM / 32, KD / 32), dim3(32, 8)>>>(Wout, wo, DIM, KD);

    // 1) QKV projection (fp16 2-pass) -> Q hi/lo + K/V plain fp16
    gemm_2p<1><<<dim3(E3 / 128, MTOT / 128), 256, GEMM_SMEM>>>(
        xh, xl, wq, nullptr, qh, ql, MTOT, E3, KD, DIM);

    // 2) sliding-window attention (fp16 2-pass) -> fp16 hi/lo ctx
    attn_mma<<<dim3(SEQ / 128, NH, BATCH), 128>>>(qh, ql, ch, cl);

    // 3) output projection (fp16 2-pass) -> fp32 out
    gemm_2p<0><<<dim3(DIM / 128, MTOT / 128), 256, GEMM_SMEM>>>(
        ch, cl, wo, out, nullptr, nullptr, MTOT, DIM, KD, 0);
}

// round 13
// speedup vs baseline: 4.5446x; 1.4830x over previous
#include <cuda_runtime.h>
#include <cuda_fp16.h>
#include <math.h>
#include <float.h>
#include <stdint.h>

#define BATCH 2
#define SEQ   2048
#define DIM   1024
#define NH    16
#define DH    64
#define WIN   512
#define E3    3072
#define MTOT  (BATCH * SEQ)   // 4096
#define KD    1024

// ---------------- scratch (device globals; no allocation) ------------------
__device__ __half g_x16[MTOT * KD];                     // x plain fp16
__device__ __half g_wq[E3 * KD];                        // Wqkv^T fp16
__device__ __half g_wo[DIM * KD];                       // Wout^T fp16
__device__ __half g_qh[MTOT * E3], g_ql[MTOT * E3];    // Q hi/lo; K/V plain in g_qh
__device__ __half g_c16[MTOT * KD];                     // ctx plain fp16

// ---------------- helpers ---------------------------------------------------
__device__ __forceinline__ void split_f16(float x, float y, uint32_t& hi, uint32_t& lo) {
    __half2 h = __floats2half2_rn(x, y);
    hi = *(uint32_t*)&h;
    __half2 l = __floats2half2_rn(x - __low2float(h), y - __high2float(h));
    lo = *(uint32_t*)&l;
}
__device__ __forceinline__ uint32_t pack_f16(float x, float y) {
    __half2 h = __floats2half2_rn(x, y);
    return *(uint32_t*)&h;
}
__device__ __forceinline__ void mma_f16(float* c, const uint32_t* a, const uint32_t* b) {
    asm volatile(
        "mma.sync.aligned.m16n8k16.row.col.f32.f16.f16.f32 "
        "{%0,%1,%2,%3}, {%4,%5,%6,%7}, {%8,%9}, {%0,%1,%2,%3};"
        : "+f"(c[0]), "+f"(c[1]), "+f"(c[2]), "+f"(c[3])
        : "r"(a[0]), "r"(a[1]), "r"(a[2]), "r"(a[3]), "r"(b[0]), "r"(b[1]));
}
__device__ __forceinline__ uint32_t smem_u32(const void* p) {
    return (uint32_t)__cvta_generic_to_shared(p);
}
#define CP16(s, g) \
    asm volatile("cp.async.cg.shared.global [%0], [%1], 16;" :: "r"(s), "l"(g))
#define CP_COMMIT() asm volatile("cp.async.commit_group;")
#define CP_WAIT(n)  asm volatile("cp.async.wait_group %0;" :: "n"(n))
#define LDSM4(r, a) \
    asm volatile("ldmatrix.sync.aligned.m8n8.x4.shared.b16 {%0,%1,%2,%3}, [%4];" \
        : "=r"((r)[0]), "=r"((r)[1]), "=r"((r)[2]), "=r"((r)[3]) : "r"(a))
#define LDSM4T(r, a) \
    asm volatile("ldmatrix.sync.aligned.m8n8.x4.trans.shared.b16 {%0,%1,%2,%3}, [%4];" \
        : "=r"((r)[0]), "=r"((r)[1]), "=r"((r)[2]), "=r"((r)[3]) : "r"(a))

// ---------------------------------------------------------------------------
// Prep kernels
// ---------------------------------------------------------------------------
__global__ __launch_bounds__(256) void convert_x_kernel(
    const float* __restrict__ x, __half* __restrict__ x16)
{
    int i = blockIdx.x * 256 + threadIdx.x;
    float4 v = ((const float4*)x)[i];
    uint32_t h0 = pack_f16(v.x, v.y);
    uint32_t h1 = pack_f16(v.z, v.w);
    ((uint2*)x16)[i] = make_uint2(h0, h1);
}

// W[K][N] fp32 -> Wt [N][K] fp16
__global__ __launch_bounds__(256) void tsplit_kernel(
    const float* __restrict__ W, __half* __restrict__ Wt, int N, int K)
{
    __shared__ float tile[32][33];
    int tx = threadIdx.x, ty = threadIdx.y;
    int n0 = blockIdx.x * 32, k0 = blockIdx.y * 32;
#pragma unroll
    for (int i = 0; i < 4; i++)
        tile[ty + 8 * i][tx] = W[(long)(k0 + ty + 8 * i) * N + n0 + tx];
    __syncthreads();
#pragma unroll
    for (int i = 0; i < 4; i++) {
        int n = ty + 8 * i;
        Wt[(long)(n0 + n) * K + k0 + tx] = __float2half_rn(tile[tx][n]);
    }
}

// ---------------------------------------------------------------------------
// fp16 single-pass GEMM: C = A*B, f32 acc. A: [M][K], B: [N][K], both fp16.
// Block tile 128x128, BK=32, 256 thr = 8 warps (2m x 4n of 64x32), 2 CTA/SM.
// MODE 0: fp32 C.
// MODE 1: qkv layout — cols < qcols: fp16 hi/lo scaled 0.125 (Q);
//         cols >= qcols: plain fp16 into Ch (K/V).
// ---------------------------------------------------------------------------
#define LDT      40                           // fp16 per smem row (32 + 8 pad)
#define A_BYTES  (128 * LDT * 2)              // 10240
#define B_BYTES  (128 * LDT * 2)              // 10240
#define STG      (A_BYTES + B_BYTES)          // 20480
#define GEMM_SMEM (2 * STG)                   // 40960

template <int MODE>
__global__ __launch_bounds__(256, 2) void gemm_1p(
    const __half* __restrict__ Ap, const __half* __restrict__ Bp,
    float* __restrict__ Cf, __half* __restrict__ Ch,
    __half* __restrict__ Cl, int M, int N, int K, int qcols)
{
    extern __shared__ char smem[];
    const uint32_t sb = smem_u32(smem);
    const int tid = threadIdx.x, wid = tid >> 5, lane = tid & 31;
    const int wm = (wid & 1) * 64, wn = (wid >> 1) * 32;
    const long arow0 = (long)blockIdx.y * 128;
    const long brow0 = (long)blockIdx.x * 128;

    float acc[4][4][4] = {};

    const uint32_t a_off =
        (uint32_t)((wm + (lane & 7) + ((lane & 8) ? 8 : 0)) * (LDT * 2)
                   + ((lane & 16) ? 16 : 0));
    const uint32_t b_off = (uint32_t)(A_BYTES
                   + (wn + (lane & 7) + ((lane & 16) ? 8 : 0)) * (LDT * 2)
                   + ((lane & 8) ? 16 : 0));

    const int nT = K / 32;

    auto issue = [&](int t) {
        const int s = t & 1, k0 = t * 32;
        const uint32_t st = sb + s * STG;
#pragma unroll
        for (int i = 0; i < 2; i++) {
            int idx = i * 256 + tid;
            int row = idx >> 2, kc = idx & 3;
            uint32_t so = st + row * (LDT * 2) + kc * 16;
            CP16(so, Ap + (arow0 + row) * K + k0 + kc * 8);
        }
#pragma unroll
        for (int i = 0; i < 2; i++) {
            int idx = i * 256 + tid;
            int row = idx >> 2, kc = idx & 3;
            uint32_t so = st + A_BYTES + row * (LDT * 2) + kc * 16;
            CP16(so, Bp + (brow0 + row) * K + k0 + kc * 8);
        }
        CP_COMMIT();
    };

    issue(0);
    for (int t = 0; t < nT; t++) {
        if (t + 1 < nT) { issue(t + 1); CP_WAIT(1); }
        else            { CP_WAIT(0); }
        __syncthreads();

        const uint32_t st = sb + (t & 1) * STG;
#pragma unroll
        for (int ks = 0; ks < 2; ks++) {
            uint32_t ah[4][4], bh[4][2];
#pragma unroll
            for (int am = 0; am < 4; am++)
                LDSM4(ah[am], st + a_off + am * (16 * LDT * 2) + ks * 32);
#pragma unroll
            for (int g = 0; g < 2; g++) {
                uint32_t a = st + b_off + g * (16 * LDT * 2) + ks * 32;
                uint32_t r[4];
                LDSM4(r, a);
                bh[2*g][0] = r[0]; bh[2*g][1] = r[1];
                bh[2*g+1][0] = r[2]; bh[2*g+1][1] = r[3];
            }
#pragma unroll
            for (int am = 0; am < 4; am++)
#pragma unroll
                for (int bn = 0; bn < 4; bn++)
                    mma_f16(acc[am][bn], ah[am], bh[bn]);
        }
        __syncthreads();
    }

    // epilogue
#pragma unroll
    for (int am = 0; am < 4; am++)
#pragma unroll
        for (int bn = 0; bn < 4; bn++) {
            int row = blockIdx.y * 128 + wm + am * 16 + (lane >> 2);
            int col = blockIdx.x * 128 + wn + bn * 8 + 2 * (lane & 3);
            if (MODE == 0) {
                *(float2*)(Cf + (long)row * N + col) =
                    make_float2(acc[am][bn][0], acc[am][bn][1]);
                *(float2*)(Cf + (long)(row + 8) * N + col) =
                    make_float2(acc[am][bn][2], acc[am][bn][3]);
            } else {
                if (col < qcols) {
                    uint32_t hh, ll;
                    split_f16(acc[am][bn][0] * 0.125f, acc[am][bn][1] * 0.125f, hh, ll);
                    *(uint32_t*)(Ch + (long)row * N + col) = hh;
                    *(uint32_t*)(Cl + (long)row * N + col) = ll;
                    split_f16(acc[am][bn][2] * 0.125f, acc[am][bn][3] * 0.125f, hh, ll);
                    *(uint32_t*)(Ch + (long)(row + 8) * N + col) = hh;
                    *(uint32_t*)(Cl + (long)(row + 8) * N + col) = ll;
                } else {
                    *(uint32_t*)(Ch + (long)row * N + col) =
                        pack_f16(acc[am][bn][0], acc[am][bn][1]);
                    *(uint32_t*)(Ch + (long)(row + 8) * N + col) =
                        pack_f16(acc[am][bn][2], acc[am][bn][3]);
                }
            }
        }
}

// ---------------------------------------------------------------------------
// Sliding-window flash attention:
//   S = (Qh + Ql) * K   (Q hi/lo 2-pass, K plain fp16)
//   O = P * V           (P plain fp16 single pass, V plain fp16)
// 128 q-rows/block, 4 warps, key tile 64. Epilogue -> plain fp16 ctx.
// ---------------------------------------------------------------------------
#define KVP 72   // fp16 per smem row (64 + 8 pad)

__global__ __launch_bounds__(128) void attn_mma(
    const __half* __restrict__ qh, const __half* __restrict__ ql,
    __half* __restrict__ ctx16)
{
    __shared__ __half Ks[64 * KVP];
    __shared__ __half Vs[64 * KVP];

    const int tid  = threadIdx.x;
    const int wid  = tid >> 5;
    const int lane = tid & 31;
    const int gid  = lane >> 2;
    const int tig  = lane & 3;
    const int i0   = blockIdx.x * 128;
    const int h    = blockIdx.y;
    const int b    = blockIdx.z;

    const long rowb = (long)b * SEQ;
    const int qcol = h * DH;
    const int kcol = DIM + h * DH;
    const int vcol = 2 * DIM + h * DH;

    uint32_t qfh[2][4][4], qfl[2][4][4];
#pragma unroll
    for (int am = 0; am < 2; am++) {
        long r = rowb + i0 + wid * 32 + am * 16 + gid;
#pragma unroll
        for (int s = 0; s < 4; s++) {
            int c = qcol + s * 16 + 2 * tig;
            qfh[am][s][0] = *(const uint32_t*)(qh + r * E3 + c);
            qfh[am][s][1] = *(const uint32_t*)(qh + (r + 8) * E3 + c);
            qfh[am][s][2] = *(const uint32_t*)(qh + r * E3 + c + 8);
            qfh[am][s][3] = *(const uint32_t*)(qh + (r + 8) * E3 + c + 8);
            qfl[am][s][0] = *(const uint32_t*)(ql + r * E3 + c);
            qfl[am][s][1] = *(const uint32_t*)(ql + (r + 8) * E3 + c);
            qfl[am][s][2] = *(const uint32_t*)(ql + r * E3 + c + 8);
            qfl[am][s][3] = *(const uint32_t*)(ql + (r + 8) * E3 + c + 8);
        }
    }

    const uint32_t ks_b = smem_u32(Ks), vs_b = smem_u32(Vs);
    const uint32_t koff = (uint32_t)(((lane & 7) + ((lane & 16) ? 8 : 0)) * (KVP * 2)
                                     + ((lane & 8) ? 16 : 0));
    const uint32_t voff = (uint32_t)(((lane & 7) + ((lane & 8) ? 8 : 0)) * (KVP * 2)
                                     + ((lane & 16) ? 16 : 0));

    float mrow[2][2], lrow[2][2], o[2][8][4] = {};
#pragma unroll
    for (int am = 0; am < 2; am++) {
        mrow[am][0] = -FLT_MAX; mrow[am][1] = -FLT_MAX;
        lrow[am][0] = 0.f;      lrow[am][1] = 0.f;
    }

    int t0 = (i0 - WIN + 1) >> 6; if (t0 < 0) t0 = 0;
    const int t1 = (i0 + 127) >> 6;

    for (int t = t0; t <= t1; t++) {
        const int kt0 = t << 6;
        __syncthreads();

#pragma unroll
        for (int i = 0; i < 4; i++) {
            int idx = i * 128 + tid;
            int row = idx >> 3, ch = idx & 7;
            long gro = (rowb + kt0 + row) * E3;
            uint32_t so = row * (KVP * 2) + ch * 16;
            CP16(ks_b + so, qh + gro + kcol + ch * 8);
            CP16(vs_b + so, qh + gro + vcol + ch * 8);
        }
        CP_COMMIT();
        CP_WAIT(0);
        __syncthreads();

        // ---- S = (Qh + Ql) K^T  (2 passes)
        float s[2][8][4] = {};
#pragma unroll
        for (int ks = 0; ks < 4; ks++) {
            uint32_t kf[8][2];
#pragma unroll
            for (int g = 0; g < 4; g++) {
                uint32_t a = koff + g * (16 * KVP * 2) + ks * 32;
                uint32_t r[4];
                LDSM4(r, ks_b + a);
                kf[2*g][0] = r[0]; kf[2*g][1] = r[1];
                kf[2*g+1][0] = r[2]; kf[2*g+1][1] = r[3];
            }
#pragma unroll
            for (int bn = 0; bn < 8; bn++)
#pragma unroll
                for (int am = 0; am < 2; am++)
                    mma_f16(s[am][bn], qfl[am][ks], kf[bn]);
#pragma unroll
            for (int bn = 0; bn < 8; bn++)
#pragma unroll
                for (int am = 0; am < 2; am++)
                    mma_f16(s[am][bn], qfh[am][ks], kf[bn]);
        }

        // ---- mask + online softmax
#pragma unroll
        for (int am = 0; am < 2; am++) {
            int qi0 = i0 + wid * 32 + am * 16 + gid;
            int qi1 = qi0 + 8;
#pragma unroll
            for (int bn = 0; bn < 8; bn++) {
                int c0 = kt0 + bn * 8 + 2 * tig, c1 = c0 + 1;
                if (c0 > qi0 || c0 < qi0 - (WIN - 1)) s[am][bn][0] = -FLT_MAX;
                if (c1 > qi0 || c1 < qi0 - (WIN - 1)) s[am][bn][1] = -FLT_MAX;
                if (c0 > qi1 || c0 < qi1 - (WIN - 1)) s[am][bn][2] = -FLT_MAX;
                if (c1 > qi1 || c1 < qi1 - (WIN - 1)) s[am][bn][3] = -FLT_MAX;
            }
            float mx0 = -FLT_MAX, mx1 = -FLT_MAX;
#pragma unroll
            for (int bn = 0; bn < 8; bn++) {
                mx0 = fmaxf(mx0, fmaxf(s[am][bn][0], s[am][bn][1]));
                mx1 = fmaxf(mx1, fmaxf(s[am][bn][2], s[am][bn][3]));
            }
            mx0 = fmaxf(mx0, __shfl_xor_sync(0xffffffffu, mx0, 1));
            mx0 = fmaxf(mx0, __shfl_xor_sync(0xffffffffu, mx0, 2));
            mx1 = fmaxf(mx1, __shfl_xor_sync(0xffffffffu, mx1, 1));
            mx1 = fmaxf(mx1, __shfl_xor_sync(0xffffffffu, mx1, 2));
            float mn0 = fmaxf(mrow[am][0], mx0);
            float mn1 = fmaxf(mrow[am][1], mx1);
            float a0 = __expf(mrow[am][0] - mn0);
            float a1 = __expf(mrow[am][1] - mn1);
            mrow[am][0] = mn0; mrow[am][1] = mn1;
            float rs0 = 0.f, rs1 = 0.f;
#pragma unroll
            for (int bn = 0; bn < 8; bn++) {
                s[am][bn][0] = __expf(s[am][bn][0] - mn0);
                s[am][bn][1] = __expf(s[am][bn][1] - mn0);
                s[am][bn][2] = __expf(s[am][bn][2] - mn1);
                s[am][bn][3] = __expf(s[am][bn][3] - mn1);
                rs0 += s[am][bn][0] + s[am][bn][1];
                rs1 += s[am][bn][2] + s[am][bn][3];
            }
            rs0 += __shfl_xor_sync(0xffffffffu, rs0, 1);
            rs0 += __shfl_xor_sync(0xffffffffu, rs0, 2);
            rs1 += __shfl_xor_sync(0xffffffffu, rs1, 1);
            rs1 += __shfl_xor_sync(0xffffffffu, rs1, 2);
            lrow[am][0] = lrow[am][0] * a0 + rs0;
            lrow[am][1] = lrow[am][1] * a1 + rs1;
#pragma unroll
            for (int bn = 0; bn < 8; bn++) {
                o[am][bn][0] *= a0; o[am][bn][1] *= a0;
                o[am][bn][2] *= a1; o[am][bn][3] *= a1;
            }
        }

        // ---- P fragments (plain fp16) from S accumulators
        uint32_t pf[2][4][4];
#pragma unroll
        for (int am = 0; am < 2; am++)
#pragma unroll
            for (int kk = 0; kk < 4; kk++) {
                pf[am][kk][0] = pack_f16(s[am][2*kk][0],   s[am][2*kk][1]);
                pf[am][kk][1] = pack_f16(s[am][2*kk][2],   s[am][2*kk][3]);
                pf[am][kk][2] = pack_f16(s[am][2*kk+1][0], s[am][2*kk+1][1]);
                pf[am][kk][3] = pack_f16(s[am][2*kk+1][2], s[am][2*kk+1][3]);
            }

        // ---- O += P V  (single pass)
#pragma unroll
        for (int kk = 0; kk < 4; kk++) {
            uint32_t vf[8][2];
#pragma unroll
            for (int g = 0; g < 4; g++) {
                uint32_t a = voff + kk * (16 * KVP * 2) + g * 32;
                uint32_t r[4];
                LDSM4T(r, vs_b + a);
                vf[2*g][0] = r[0]; vf[2*g][1] = r[1];
                vf[2*g+1][0] = r[2]; vf[2*g+1][1] = r[3];
            }
#pragma unroll
            for (int bn = 0; bn < 8; bn++)
#pragma unroll
                for (int am = 0; am < 2; am++)
                    mma_f16(o[am][bn], pf[am][kk], vf[bn]);
        }
    }

    // ---- epilogue: normalize, plain fp16 ctx
#pragma unroll
    for (int am = 0; am < 2; am++) {
        float inv0 = 1.f / lrow[am][0];
        float inv1 = 1.f / lrow[am][1];
        long r0 = rowb + i0 + wid * 32 + am * 16 + gid;
#pragma unroll
        for (int bn = 0; bn < 8; bn++) {
            int col = h * DH + bn * 8 + 2 * tig;
            *(uint32_t*)(ctx16 + r0 * DIM + col) =
                pack_f16(o[am][bn][0] * inv0, o[am][bn][1] * inv0);
            *(uint32_t*)(ctx16 + (r0 + 8) * DIM + col) =
                pack_f16(o[am][bn][2] * inv1, o[am][bn][3] * inv1);
        }
    }
}

// ---------------------------------------------------------------------------
extern "C" void kernel_launch(void* const* d_in, const int* in_sizes, int n_in,
                              void* d_out, int out_size)
{
    (void)in_sizes; (void)n_in; (void)out_size;
    const float* x    = (const float*)d_in[0];
    const float* Wqkv = (const float*)d_in[1];
    const float* Wout = (const float*)d_in[2];
    float* out = (float*)d_out;

    __half *x16, *wq, *wo, *qh, *ql, *c16;
    cudaGetSymbolAddress((void**)&x16, g_x16);
    cudaGetSymbolAddress((void**)&wq,  g_wq);
    cudaGetSymbolAddress((void**)&wo,  g_wo);
    cudaGetSymbolAddress((void**)&qh,  g_qh);
    cudaGetSymbolAddress((void**)&ql,  g_ql);
    cudaGetSymbolAddress((void**)&c16, g_c16);

    cudaFuncSetAttribute(gemm_1p<0>,
                         cudaFuncAttributeMaxDynamicSharedMemorySize, GEMM_SMEM);
    cudaFuncSetAttribute(gemm_1p<1>,
                         cudaFuncAttributeMaxDynamicSharedMemorySize, GEMM_SMEM);

    // prep
    convert_x_kernel<<<(MTOT * KD) / 1024, 256>>>(x, x16);
    tsplit_kernel<<<dim3(E3 / 32, KD / 32), dim3(32, 8)>>>(Wqkv, wq, E3, KD);
    tsplit_kernel<<<dim3(DIM / 32, KD / 32), dim3(32, 8)>>>(Wout, wo, DIM, KD);

    // 1) QKV projection (single pass) -> Q hi/lo + K/V plain fp16
    gemm_1p<1><<<dim3(E3 / 128, MTOT / 128), 256, GEMM_SMEM>>>(
        x16, wq, nullptr, qh, ql, MTOT, E3, KD, DIM);

    // 2) sliding-window attention -> plain fp16 ctx
    attn_mma<<<dim3(SEQ / 128, NH, BATCH), 128>>>(qh, ql, c16);

    // 3) output projection (single pass) -> fp32 out
    gemm_1p<0><<<dim3(DIM / 128, MTOT / 128), 256, GEMM_SMEM>>>(
        c16, wo, out, nullptr, nullptr, MTOT, DIM, KD, 0);
}

// round 15
// speedup vs baseline: 4.8063x; 1.0576x over previous
#include <cuda_runtime.h>
#include <cuda_fp16.h>
#include <math.h>
#include <float.h>
#include <stdint.h>

#define BATCH 2
#define SEQ   2048
#define DIM   1024
#define NH    16
#define DH    64
#define WIN   512
#define E3    3072
#define MTOT  (BATCH * SEQ)   // 4096
#define KD    1024

// ---------------- scratch (device globals; no allocation) ------------------
__device__ __half g_x16[MTOT * KD];     // x plain fp16
__device__ __half g_wq[E3 * KD];        // Wqkv^T fp16
__device__ __half g_wo[DIM * KD];       // Wout^T fp16
__device__ __half g_qkv[MTOT * E3];     // qkv plain fp16 (Q pre-scaled)
__device__ __half g_c16[MTOT * KD];     // ctx plain fp16

// ---------------- helpers ---------------------------------------------------
__device__ __forceinline__ uint32_t pack_f16(float x, float y) {
    __half2 h = __floats2half2_rn(x, y);
    return *(uint32_t*)&h;
}
__device__ __forceinline__ void mma_f16(float* c, const uint32_t* a, const uint32_t* b) {
    asm volatile(
        "mma.sync.aligned.m16n8k16.row.col.f32.f16.f16.f32 "
        "{%0,%1,%2,%3}, {%4,%5,%6,%7}, {%8,%9}, {%0,%1,%2,%3};"
        : "+f"(c[0]), "+f"(c[1]), "+f"(c[2]), "+f"(c[3])
        : "r"(a[0]), "r"(a[1]), "r"(a[2]), "r"(a[3]), "r"(b[0]), "r"(b[1]));
}
__device__ __forceinline__ uint32_t smem_u32(const void* p) {
    return (uint32_t)__cvta_generic_to_shared(p);
}
#define CP16(s, g) \
    asm volatile("cp.async.cg.shared.global [%0], [%1], 16;" :: "r"(s), "l"(g))
#define CP_COMMIT() asm volatile("cp.async.commit_group;")
#define CP_WAIT(n)  asm volatile("cp.async.wait_group %0;" :: "n"(n))
#define LDSM4(r, a) \
    asm volatile("ldmatrix.sync.aligned.m8n8.x4.shared.b16 {%0,%1,%2,%3}, [%4];" \
        : "=r"((r)[0]), "=r"((r)[1]), "=r"((r)[2]), "=r"((r)[3]) : "r"(a))
#define LDSM4T(r, a) \
    asm volatile("ldmatrix.sync.aligned.m8n8.x4.trans.shared.b16 {%0,%1,%2,%3}, [%4];" \
        : "=r"((r)[0]), "=r"((r)[1]), "=r"((r)[2]), "=r"((r)[3]) : "r"(a))

// ---------------------------------------------------------------------------
// Prep kernels
// ---------------------------------------------------------------------------
__global__ __launch_bounds__(256) void convert_x_kernel(
    const float* __restrict__ x, __half* __restrict__ x16)
{
    int i = blockIdx.x * 256 + threadIdx.x;
    float4 v = ((const float4*)x)[i];
    ((uint2*)x16)[i] = make_uint2(pack_f16(v.x, v.y), pack_f16(v.z, v.w));
}

// W[K][N] fp32 -> Wt [N][K] fp16
__global__ __launch_bounds__(256) void tsplit_kernel(
    const float* __restrict__ W, __half* __restrict__ Wt, int N, int K)
{
    __shared__ float tile[32][33];
    int tx = threadIdx.x, ty = threadIdx.y;
    int n0 = blockIdx.x * 32, k0 = blockIdx.y * 32;
#pragma unroll
    for (int i = 0; i < 4; i++)
        tile[ty + 8 * i][tx] = W[(long)(k0 + ty + 8 * i) * N + n0 + tx];
    __syncthreads();
#pragma unroll
    for (int i = 0; i < 4; i++) {
        int n = ty + 8 * i;
        Wt[(long)(n0 + n) * K + k0 + tx] = __float2half_rn(tile[tx][n]);
    }
}

// ---------------------------------------------------------------------------
// fp16 single-pass GEMM: C = A*B, f32 acc. A: [M][K], B: [N][K], both fp16.
// Block tile 128x128, BK=32, 256 thr = 8 warps (2m x 4n of 64x32), 2 CTA/SM.
// MODE 0: fp32 C.  MODE 1: plain fp16 C, cols < qcols scaled by 0.125 (Q).
// ---------------------------------------------------------------------------
#define LDT      40                           // fp16 per smem row (32 + 8 pad)
#define A_BYTES  (128 * LDT * 2)              // 10240
#define B_BYTES  (128 * LDT * 2)              // 10240
#define STG      (A_BYTES + B_BYTES)          // 20480
#define GEMM_SMEM (2 * STG)                   // 40960

template <int MODE>
__global__ __launch_bounds__(256, 2) void gemm_1p(
    const __half* __restrict__ Ap, const __half* __restrict__ Bp,
    float* __restrict__ Cf, __half* __restrict__ Ch,
    int M, int N, int K, int qcols)
{
    extern __shared__ char smem[];
    const uint32_t sb = smem_u32(smem);
    const int tid = threadIdx.x, wid = tid >> 5, lane = tid & 31;
    const int wm = (wid & 1) * 64, wn = (wid >> 1) * 32;
    const long arow0 = (long)blockIdx.y * 128;
    const long brow0 = (long)blockIdx.x * 128;

    float acc[4][4][4] = {};

    const uint32_t a_off =
        (uint32_t)((wm + (lane & 7) + ((lane & 8) ? 8 : 0)) * (LDT * 2)
                   + ((lane & 16) ? 16 : 0));
    const uint32_t b_off = (uint32_t)(A_BYTES
                   + (wn + (lane & 7) + ((lane & 16) ? 8 : 0)) * (LDT * 2)
                   + ((lane & 8) ? 16 : 0));

    const int nT = K / 32;

    auto issue = [&](int t) {
        const int s = t & 1, k0 = t * 32;
        const uint32_t st = sb + s * STG;
#pragma unroll
        for (int i = 0; i < 2; i++) {
            int idx = i * 256 + tid;
            int row = idx >> 2, kc = idx & 3;
            CP16(st + row * (LDT * 2) + kc * 16,
                 Ap + (arow0 + row) * K + k0 + kc * 8);
        }
#pragma unroll
        for (int i = 0; i < 2; i++) {
            int idx = i * 256 + tid;
            int row = idx >> 2, kc = idx & 3;
            CP16(st + A_BYTES + row * (LDT * 2) + kc * 16,
                 Bp + (brow0 + row) * K + k0 + kc * 8);
        }
        CP_COMMIT();
    };

    issue(0);
    for (int t = 0; t < nT; t++) {
        if (t + 1 < nT) { issue(t + 1); CP_WAIT(1); }
        else            { CP_WAIT(0); }
        __syncthreads();

        const uint32_t st = sb + (t & 1) * STG;
#pragma unroll
        for (int ks = 0; ks < 2; ks++) {
            uint32_t ah[4][4], bh[4][2];
#pragma unroll
            for (int am = 0; am < 4; am++)
                LDSM4(ah[am], st + a_off + am * (16 * LDT * 2) + ks * 32);
#pragma unroll
            for (int g = 0; g < 2; g++) {
                uint32_t a = st + b_off + g * (16 * LDT * 2) + ks * 32;
                uint32_t r[4];
                LDSM4(r, a);
                bh[2*g][0] = r[0]; bh[2*g][1] = r[1];
                bh[2*g+1][0] = r[2]; bh[2*g+1][1] = r[3];
            }
#pragma unroll
            for (int am = 0; am < 4; am++)
#pragma unroll
                for (int bn = 0; bn < 4; bn++)
                    mma_f16(acc[am][bn], ah[am], bh[bn]);
        }
        __syncthreads();
    }

    // epilogue
#pragma unroll
    for (int am = 0; am < 4; am++)
#pragma unroll
        for (int bn = 0; bn < 4; bn++) {
            int row = blockIdx.y * 128 + wm + am * 16 + (lane >> 2);
            int col = blockIdx.x * 128 + wn + bn * 8 + 2 * (lane & 3);
            if (MODE == 0) {
                *(float2*)(Cf + (long)row * N + col) =
                    make_float2(acc[am][bn][0], acc[am][bn][1]);
                *(float2*)(Cf + (long)(row + 8) * N + col) =
                    make_float2(acc[am][bn][2], acc[am][bn][3]);
            } else {
                float scl = (col < qcols) ? 0.125f : 1.0f;
                *(uint32_t*)(Ch + (long)row * N + col) =
                    pack_f16(acc[am][bn][0] * scl, acc[am][bn][1] * scl);
                *(uint32_t*)(Ch + (long)(row + 8) * N + col) =
                    pack_f16(acc[am][bn][2] * scl, acc[am][bn][3] * scl);
            }
        }
}

// ---------------------------------------------------------------------------
// Sliding-window flash attention, all-plain fp16 single-pass:
//   S = Q * K^T ; O = P * V. 128 q-rows/block, 4 warps, key tile 64.
// ---------------------------------------------------------------------------
#define KVP 72   // fp16 per smem row (64 + 8 pad)

__global__ __launch_bounds__(128) void attn_mma(
    const __half* __restrict__ qkv, __half* __restrict__ ctx16)
{
    __shared__ __half Ks[64 * KVP];
    __shared__ __half Vs[64 * KVP];

    const int tid  = threadIdx.x;
    const int wid  = tid >> 5;
    const int lane = tid & 31;
    const int gid  = lane >> 2;
    const int tig  = lane & 3;
    const int i0   = blockIdx.x * 128;
    const int h    = blockIdx.y;
    const int b    = blockIdx.z;

    const long rowb = (long)b * SEQ;
    const int qcol = h * DH;
    const int kcol = DIM + h * DH;
    const int vcol = 2 * DIM + h * DH;

    // Q fragments (pre-scaled plain fp16)
    uint32_t qf[2][4][4];
#pragma unroll
    for (int am = 0; am < 2; am++) {
        long r = rowb + i0 + wid * 32 + am * 16 + gid;
#pragma unroll
        for (int s = 0; s < 4; s++) {
            int c = qcol + s * 16 + 2 * tig;
            qf[am][s][0] = *(const uint32_t*)(qkv + r * E3 + c);
            qf[am][s][1] = *(const uint32_t*)(qkv + (r + 8) * E3 + c);
            qf[am][s][2] = *(const uint32_t*)(qkv + r * E3 + c + 8);
            qf[am][s][3] = *(const uint32_t*)(qkv + (r + 8) * E3 + c + 8);
        }
    }

    const uint32_t ks_b = smem_u32(Ks), vs_b = smem_u32(Vs);
    const uint32_t koff = (uint32_t)(((lane & 7) + ((lane & 16) ? 8 : 0)) * (KVP * 2)
                                     + ((lane & 8) ? 16 : 0));
    const uint32_t voff = (uint32_t)(((lane & 7) + ((lane & 8) ? 8 : 0)) * (KVP * 2)
                                     + ((lane & 16) ? 16 : 0));

    float mrow[2][2], lrow[2][2], o[2][8][4] = {};
#pragma unroll
    for (int am = 0; am < 2; am++) {
        mrow[am][0] = -FLT_MAX; mrow[am][1] = -FLT_MAX;
        lrow[am][0] = 0.f;      lrow[am][1] = 0.f;
    }

    int t0 = (i0 - WIN + 1) >> 6; if (t0 < 0) t0 = 0;
    const int t1 = (i0 + 127) >> 6;

    for (int t = t0; t <= t1; t++) {
        const int kt0 = t << 6;
        __syncthreads();

#pragma unroll
        for (int i = 0; i < 4; i++) {
            int idx = i * 128 + tid;
            int row = idx >> 3, ch = idx & 7;
            long gro = (rowb + kt0 + row) * E3;
            uint32_t so = row * (KVP * 2) + ch * 16;
            CP16(ks_b + so, qkv + gro + kcol + ch * 8);
            CP16(vs_b + so, qkv + gro + vcol + ch * 8);
        }
        CP_COMMIT();
        CP_WAIT(0);
        __syncthreads();

        // ---- S = Q K^T  (single pass)
        float s[2][8][4] = {};
#pragma unroll
        for (int ks = 0; ks < 4; ks++) {
            uint32_t kf[8][2];
#pragma unroll
            for (int g = 0; g < 4; g++) {
                uint32_t a = koff + g * (16 * KVP * 2) + ks * 32;
                uint32_t r[4];
                LDSM4(r, ks_b + a);
                kf[2*g][0] = r[0]; kf[2*g][1] = r[1];
                kf[2*g+1][0] = r[2]; kf[2*g+1][1] = r[3];
            }
#pragma unroll
            for (int bn = 0; bn < 8; bn++)
#pragma unroll
                for (int am = 0; am < 2; am++)
                    mma_f16(s[am][bn], qf[am][ks], kf[bn]);
        }

        // ---- mask + online softmax
#pragma unroll
        for (int am = 0; am < 2; am++) {
            int qi0 = i0 + wid * 32 + am * 16 + gid;
            int qi1 = qi0 + 8;
#pragma unroll
            for (int bn = 0; bn < 8; bn++) {
                int c0 = kt0 + bn * 8 + 2 * tig, c1 = c0 + 1;
                if (c0 > qi0 || c0 < qi0 - (WIN - 1)) s[am][bn][0] = -FLT_MAX;
                if (c1 > qi0 || c1 < qi0 - (WIN - 1)) s[am][bn][1] = -FLT_MAX;
                if (c0 > qi1 || c0 < qi1 - (WIN - 1)) s[am][bn][2] = -FLT_MAX;
                if (c1 > qi1 || c1 < qi1 - (WIN - 1)) s[am][bn][3] = -FLT_MAX;
            }
            float mx0 = -FLT_MAX, mx1 = -FLT_MAX;
#pragma unroll
            for (int bn = 0; bn < 8; bn++) {
                mx0 = fmaxf(mx0, fmaxf(s[am][bn][0], s[am][bn][1]));
                mx1 = fmaxf(mx1, fmaxf(s[am][bn][2], s[am][bn][3]));
            }
            mx0 = fmaxf(mx0, __shfl_xor_sync(0xffffffffu, mx0, 1));
            mx0 = fmaxf(mx0, __shfl_xor_sync(0xffffffffu, mx0, 2));
            mx1 = fmaxf(mx1, __shfl_xor_sync(0xffffffffu, mx1, 1));
            mx1 = fmaxf(mx1, __shfl_xor_sync(0xffffffffu, mx1, 2));
            float mn0 = fmaxf(mrow[am][0], mx0);
            float mn1 = fmaxf(mrow[am][1], mx1);
            float a0 = __expf(mrow[am][0] - mn0);
            float a1 = __expf(mrow[am][1] - mn1);
            mrow[am][0] = mn0; mrow[am][1] = mn1;
            float rs0 = 0.f, rs1 = 0.f;
#pragma unroll
            for (int bn = 0; bn < 8; bn++) {
                s[am][bn][0] = __expf(s[am][bn][0] - mn0);
                s[am][bn][1] = __expf(s[am][bn][1] - mn0);
                s[am][bn][2] = __expf(s[am][bn][2] - mn1);
                s[am][bn][3] = __expf(s[am][bn][3] - mn1);
                rs0 += s[am][bn][0] + s[am][bn][1];
                rs1 += s[am][bn][2] + s[am][bn][3];
            }
            rs0 += __shfl_xor_sync(0xffffffffu, rs0, 1);
            rs0 += __shfl_xor_sync(0xffffffffu, rs0, 2);
            rs1 += __shfl_xor_sync(0xffffffffu, rs1, 1);
            rs1 += __shfl_xor_sync(0xffffffffu, rs1, 2);
            lrow[am][0] = lrow[am][0] * a0 + rs0;
            lrow[am][1] = lrow[am][1] * a1 + rs1;
#pragma unroll
            for (int bn = 0; bn < 8; bn++) {
                o[am][bn][0] *= a0; o[am][bn][1] *= a0;
                o[am][bn][2] *= a1; o[am][bn][3] *= a1;
            }
        }

        // ---- P fragments (plain fp16) from S accumulators
        uint32_t pf[2][4][4];
#pragma unroll
        for (int am = 0; am < 2; am++)
#pragma unroll
            for (int kk = 0; kk < 4; kk++) {
                pf[am][kk][0] = pack_f16(s[am][2*kk][0],   s[am][2*kk][1]);
                pf[am][kk][1] = pack_f16(s[am][2*kk][2],   s[am][2*kk][3]);
                pf[am][kk][2] = pack_f16(s[am][2*kk+1][0], s[am][2*kk+1][1]);
                pf[am][kk][3] = pack_f16(s[am][2*kk+1][2], s[am][2*kk+1][3]);
            }

        // ---- O += P V  (single pass)
#pragma unroll
        for (int kk = 0; kk < 4; kk++) {
            uint32_t vf[8][2];
#pragma unroll
            for (int g = 0; g < 4; g++) {
                uint32_t a = voff + kk * (16 * KVP * 2) + g * 32;
                uint32_t r[4];
                LDSM4T(r, vs_b + a);
                vf[2*g][0] = r[0]; vf[2*g][1] = r[1];
                vf[2*g+1][0] = r[2]; vf[2*g+1][1] = r[3];
            }
#pragma unroll
            for (int bn = 0; bn < 8; bn++)
#pragma unroll
                for (int am = 0; am < 2; am++)
                    mma_f16(o[am][bn], pf[am][kk], vf[bn]);
        }
    }

    // ---- epilogue: normalize, plain fp16 ctx
#pragma unroll
    for (int am = 0; am < 2; am++) {
        float inv0 = 1.f / lrow[am][0];
        float inv1 = 1.f / lrow[am][1];
        long r0 = rowb + i0 + wid * 32 + am * 16 + gid;
#pragma unroll
        for (int bn = 0; bn < 8; bn++) {
            int col = h * DH + bn * 8 + 2 * tig;
            *(uint32_t*)(ctx16 + r0 * DIM + col) =
                pack_f16(o[am][bn][0] * inv0, o[am][bn][1] * inv0);
            *(uint32_t*)(ctx16 + (r0 + 8) * DIM + col) =
                pack_f16(o[am][bn][2] * inv1, o[am][bn][3] * inv1);
        }
    }
}

// ---------------------------------------------------------------------------
extern "C" void kernel_launch(void* const* d_in, const int* in_sizes, int n_in,
                              void* d_out, int out_size)
{
    (void)in_sizes; (void)n_in; (void)out_size;
    const float* x    = (const float*)d_in[0];
    const float* Wqkv = (const float*)d_in[1];
    const float* Wout = (const float*)d_in[2];
    float* out = (float*)d_out;

    __half *x16, *wq, *wo, *qkv, *c16;
    cudaGetSymbolAddress((void**)&x16, g_x16);
    cudaGetSymbolAddress((void**)&wq,  g_wq);
    cudaGetSymbolAddress((void**)&wo,  g_wo);
    cudaGetSymbolAddress((void**)&qkv, g_qkv);
    cudaGetSymbolAddress((void**)&c16, g_c16);

    cudaFuncSetAttribute(gemm_1p<0>,
                         cudaFuncAttributeMaxDynamicSharedMemorySize, GEMM_SMEM);
    cudaFuncSetAttribute(gemm_1p<1>,
                         cudaFuncAttributeMaxDynamicSharedMemorySize, GEMM_SMEM);

    // prep
    convert_x_kernel<<<(MTOT * KD) / 1024, 256>>>(x, x16);
    tsplit_kernel<<<dim3(E3 / 32, KD / 32), dim3(32, 8)>>>(Wqkv, wq, E3, KD);
    tsplit_kernel<<<dim3(DIM / 32, KD / 32), dim3(32, 8)>>>(Wout, wo, DIM, KD);

    // 1) QKV projection (single pass) -> plain fp16 qkv (Q pre-scaled)
    gemm_1p<1><<<dim3(E3 / 128, MTOT / 128), 256, GEMM_SMEM>>>(
        x16, wq, nullptr, qkv, MTOT, E3, KD, DIM);

    // 2) sliding-window attention (single pass) -> plain fp16 ctx
    attn_mma<<<dim3(SEQ / 128, NH, BATCH), 128>>>(qkv, c16);

    // 3) output projection (single pass) -> fp32 out
    gemm_1p<0><<<dim3(DIM / 128, MTOT / 128), 256, GEMM_SMEM>>>(
        c16, wo, out, nullptr, MTOT, DIM, KD, 0);
}

// round 16
// speedup vs baseline: 5.4518x; 1.1343x over previous
#include <cuda_runtime.h>
#include <cuda_fp16.h>
#include <math.h>
#include <float.h>
#include <stdint.h>

#define BATCH 2
#define SEQ   2048
#define DIM   1024
#define NH    16
#define DH    64
#define WIN   512
#define E3    3072
#define MTOT  (BATCH * SEQ)   // 4096
#define KD    1024

// ---------------- scratch (device globals; no allocation) ------------------
__device__ __half g_x16[MTOT * KD];     // x plain fp16
__device__ __half g_wq[E3 * KD];        // Wqkv^T fp16
__device__ __half g_wo[DIM * KD];       // Wout^T fp16
__device__ __half g_qkv[MTOT * E3];     // qkv plain fp16 (Q pre-scaled)
__device__ __half g_c16[MTOT * KD];     // ctx plain fp16

// ---------------- helpers ---------------------------------------------------
__device__ __forceinline__ uint32_t pack_f16(float x, float y) {
    __half2 h = __floats2half2_rn(x, y);
    return *(uint32_t*)&h;
}
__device__ __forceinline__ void mma_f16(float* c, const uint32_t* a, const uint32_t* b) {
    asm volatile(
        "mma.sync.aligned.m16n8k16.row.col.f32.f16.f16.f32 "
        "{%0,%1,%2,%3}, {%4,%5,%6,%7}, {%8,%9}, {%0,%1,%2,%3};"
        : "+f"(c[0]), "+f"(c[1]), "+f"(c[2]), "+f"(c[3])
        : "r"(a[0]), "r"(a[1]), "r"(a[2]), "r"(a[3]), "r"(b[0]), "r"(b[1]));
}
__device__ __forceinline__ uint32_t smem_u32(const void* p) {
    return (uint32_t)__cvta_generic_to_shared(p);
}
#define CP16(s, g) \
    asm volatile("cp.async.cg.shared.global [%0], [%1], 16;" :: "r"(s), "l"(g))
#define CP_COMMIT() asm volatile("cp.async.commit_group;")
#define CP_WAIT(n)  asm volatile("cp.async.wait_group %0;" :: "n"(n))
#define LDSM4(r, a) \
    asm volatile("ldmatrix.sync.aligned.m8n8.x4.shared.b16 {%0,%1,%2,%3}, [%4];" \
        : "=r"((r)[0]), "=r"((r)[1]), "=r"((r)[2]), "=r"((r)[3]) : "r"(a))
#define LDSM4T(r, a) \
    asm volatile("ldmatrix.sync.aligned.m8n8.x4.trans.shared.b16 {%0,%1,%2,%3}, [%4];" \
        : "=r"((r)[0]), "=r"((r)[1]), "=r"((r)[2]), "=r"((r)[3]) : "r"(a))

// ---------------------------------------------------------------------------
// Prep kernels
// ---------------------------------------------------------------------------
__global__ __launch_bounds__(256) void convert_x_kernel(
    const float* __restrict__ x, __half* __restrict__ x16)
{
    int i = blockIdx.x * 256 + threadIdx.x;
    float4 v = ((const float4*)x)[i];
    ((uint2*)x16)[i] = make_uint2(pack_f16(v.x, v.y), pack_f16(v.z, v.w));
}

// W[K][N] fp32 -> Wt [N][K] fp16
__global__ __launch_bounds__(256) void tsplit_kernel(
    const float* __restrict__ W, __half* __restrict__ Wt, int N, int K)
{
    __shared__ float tile[32][33];
    int tx = threadIdx.x, ty = threadIdx.y;
    int n0 = blockIdx.x * 32, k0 = blockIdx.y * 32;
#pragma unroll
    for (int i = 0; i < 4; i++)
        tile[ty + 8 * i][tx] = W[(long)(k0 + ty + 8 * i) * N + n0 + tx];
    __syncthreads();
#pragma unroll
    for (int i = 0; i < 4; i++) {
        int n = ty + 8 * i;
        Wt[(long)(n0 + n) * K + k0 + tx] = __float2half_rn(tile[tx][n]);
    }
}

// ---------------------------------------------------------------------------
// fp16 single-pass GEMM: C = A*B, f32 acc. A: [M][K], B: [N][K], both fp16.
// Block tile 128x128, BK=64, 256 thr = 8 warps (2m x 4n of 64x32), 2 CTA/SM.
// MODE 0: fp32 C.  MODE 1: plain fp16 C, cols < qcols scaled by 0.125 (Q).
// ---------------------------------------------------------------------------
#define LDT      72                           // fp16 per smem row (64 + 8 pad)
#define A_BYTES  (128 * LDT * 2)              // 18432
#define B_BYTES  (128 * LDT * 2)              // 18432
#define STG      (A_BYTES + B_BYTES)          // 36864
#define GEMM_SMEM (2 * STG)                   // 73728

template <int MODE>
__global__ __launch_bounds__(256, 2) void gemm_1p(
    const __half* __restrict__ Ap, const __half* __restrict__ Bp,
    float* __restrict__ Cf, __half* __restrict__ Ch,
    int M, int N, int K, int qcols)
{
    extern __shared__ char smem[];
    const uint32_t sb = smem_u32(smem);
    const int tid = threadIdx.x, wid = tid >> 5, lane = tid & 31;
    const int wm = (wid & 1) * 64, wn = (wid >> 1) * 32;
    const long arow0 = (long)blockIdx.y * 128;
    const long brow0 = (long)blockIdx.x * 128;

    float acc[4][4][4] = {};

    const uint32_t a_off =
        (uint32_t)((wm + (lane & 7) + ((lane & 8) ? 8 : 0)) * (LDT * 2)
                   + ((lane & 16) ? 16 : 0));
    const uint32_t b_off = (uint32_t)(A_BYTES
                   + (wn + (lane & 7) + ((lane & 16) ? 8 : 0)) * (LDT * 2)
                   + ((lane & 8) ? 16 : 0));

    const int nT = K / 64;

    auto issue = [&](int t) {
        const int s = t & 1, k0 = t * 64;
        const uint32_t st = sb + s * STG;
        // A: 1024 chunks (128 rows x 8 chunks of 16B)
#pragma unroll
        for (int i = 0; i < 4; i++) {
            int idx = i * 256 + tid;
            int row = idx >> 3, kc = idx & 7;
            CP16(st + row * (LDT * 2) + kc * 16,
                 Ap + (arow0 + row) * K + k0 + kc * 8);
        }
        // B: 1024 chunks
#pragma unroll
        for (int i = 0; i < 4; i++) {
            int idx = i * 256 + tid;
            int row = idx >> 3, kc = idx & 7;
            CP16(st + A_BYTES + row * (LDT * 2) + kc * 16,
                 Bp + (brow0 + row) * K + k0 + kc * 8);
        }
        CP_COMMIT();
    };

    issue(0);
    for (int t = 0; t < nT; t++) {
        if (t + 1 < nT) { issue(t + 1); CP_WAIT(1); }
        else            { CP_WAIT(0); }
        __syncthreads();

        const uint32_t st = sb + (t & 1) * STG;
#pragma unroll
        for (int ks = 0; ks < 4; ks++) {
            uint32_t ah[4][4], bh[4][2];
#pragma unroll
            for (int am = 0; am < 4; am++)
                LDSM4(ah[am], st + a_off + am * (16 * LDT * 2) + ks * 32);
#pragma unroll
            for (int g = 0; g < 2; g++) {
                uint32_t a = st + b_off + g * (16 * LDT * 2) + ks * 32;
                uint32_t r[4];
                LDSM4(r, a);
                bh[2*g][0] = r[0]; bh[2*g][1] = r[1];
                bh[2*g+1][0] = r[2]; bh[2*g+1][1] = r[3];
            }
#pragma unroll
            for (int am = 0; am < 4; am++)
#pragma unroll
                for (int bn = 0; bn < 4; bn++)
                    mma_f16(acc[am][bn], ah[am], bh[bn]);
        }
        __syncthreads();
    }

    // epilogue
#pragma unroll
    for (int am = 0; am < 4; am++)
#pragma unroll
        for (int bn = 0; bn < 4; bn++) {
            int row = blockIdx.y * 128 + wm + am * 16 + (lane >> 2);
            int col = blockIdx.x * 128 + wn + bn * 8 + 2 * (lane & 3);
            if (MODE == 0) {
                *(float2*)(Cf + (long)row * N + col) =
                    make_float2(acc[am][bn][0], acc[am][bn][1]);
                *(float2*)(Cf + (long)(row + 8) * N + col) =
                    make_float2(acc[am][bn][2], acc[am][bn][3]);
            } else {
                float scl = (col < qcols) ? 0.125f : 1.0f;
                *(uint32_t*)(Ch + (long)row * N + col) =
                    pack_f16(acc[am][bn][0] * scl, acc[am][bn][1] * scl);
                *(uint32_t*)(Ch + (long)(row + 8) * N + col) =
                    pack_f16(acc[am][bn][2] * scl, acc[am][bn][3] * scl);
            }
        }
}

// ---------------------------------------------------------------------------
// Sliding-window flash attention, all-plain fp16 single-pass (R15-proven):
//   S = Q * K^T ; O = P * V. 128 q-rows/block, 4 warps, key tile 64.
// ---------------------------------------------------------------------------
#define KVP 72   // fp16 per smem row (64 + 8 pad)

__global__ __launch_bounds__(128) void attn_mma(
    const __half* __restrict__ qkv, __half* __restrict__ ctx16)
{
    __shared__ __half Ks[64 * KVP];
    __shared__ __half Vs[64 * KVP];

    const int tid  = threadIdx.x;
    const int wid  = tid >> 5;
    const int lane = tid & 31;
    const int gid  = lane >> 2;
    const int tig  = lane & 3;
    const int i0   = blockIdx.x * 128;
    const int h    = blockIdx.y;
    const int b    = blockIdx.z;

    const long rowb = (long)b * SEQ;
    const int qcol = h * DH;
    const int kcol = DIM + h * DH;
    const int vcol = 2 * DIM + h * DH;

    uint32_t qf[2][4][4];
#pragma unroll
    for (int am = 0; am < 2; am++) {
        long r = rowb + i0 + wid * 32 + am * 16 + gid;
#pragma unroll
        for (int s = 0; s < 4; s++) {
            int c = qcol + s * 16 + 2 * tig;
            qf[am][s][0] = *(const uint32_t*)(qkv + r * E3 + c);
            qf[am][s][1] = *(const uint32_t*)(qkv + (r + 8) * E3 + c);
            qf[am][s][2] = *(const uint32_t*)(qkv + r * E3 + c + 8);
            qf[am][s][3] = *(const uint32_t*)(qkv + (r + 8) * E3 + c + 8);
        }
    }

    const uint32_t ks_b = smem_u32(Ks), vs_b = smem_u32(Vs);
    const uint32_t koff = (uint32_t)(((lane & 7) + ((lane & 16) ? 8 : 0)) * (KVP * 2)
                                     + ((lane & 8) ? 16 : 0));
    const uint32_t voff = (uint32_t)(((lane & 7) + ((lane & 8) ? 8 : 0)) * (KVP * 2)
                                     + ((lane & 16) ? 16 : 0));

    float mrow[2][2], lrow[2][2], o[2][8][4] = {};
#pragma unroll
    for (int am = 0; am < 2; am++) {
        mrow[am][0] = -FLT_MAX; mrow[am][1] = -FLT_MAX;
        lrow[am][0] = 0.f;      lrow[am][1] = 0.f;
    }

    int t0 = (i0 - WIN + 1) >> 6; if (t0 < 0) t0 = 0;
    const int t1 = (i0 + 127) >> 6;

    for (int t = t0; t <= t1; t++) {
        const int kt0 = t << 6;
        __syncthreads();

#pragma unroll
        for (int i = 0; i < 4; i++) {
            int idx = i * 128 + tid;
            int row = idx >> 3, ch = idx & 7;
            long gro = (rowb + kt0 + row) * E3;
            uint32_t so = row * (KVP * 2) + ch * 16;
            CP16(ks_b + so, qkv + gro + kcol + ch * 8);
            CP16(vs_b + so, qkv + gro + vcol + ch * 8);
        }
        CP_COMMIT();
        CP_WAIT(0);
        __syncthreads();

        float s[2][8][4] = {};
#pragma unroll
        for (int ks = 0; ks < 4; ks++) {
            uint32_t kf[8][2];
#pragma unroll
            for (int g = 0; g < 4; g++) {
                uint32_t a = koff + g * (16 * KVP * 2) + ks * 32;
                uint32_t r[4];
                LDSM4(r, ks_b + a);
                kf[2*g][0] = r[0]; kf[2*g][1] = r[1];
                kf[2*g+1][0] = r[2]; kf[2*g+1][1] = r[3];
            }
#pragma unroll
            for (int bn = 0; bn < 8; bn++)
#pragma unroll
                for (int am = 0; am < 2; am++)
                    mma_f16(s[am][bn], qf[am][ks], kf[bn]);
        }

#pragma unroll
        for (int am = 0; am < 2; am++) {
            int qi0 = i0 + wid * 32 + am * 16 + gid;
            int qi1 = qi0 + 8;
#pragma unroll
            for (int bn = 0; bn < 8; bn++) {
                int c0 = kt0 + bn * 8 + 2 * tig, c1 = c0 + 1;
                if (c0 > qi0 || c0 < qi0 - (WIN - 1)) s[am][bn][0] = -FLT_MAX;
                if (c1 > qi0 || c1 < qi0 - (WIN - 1)) s[am][bn][1] = -FLT_MAX;
                if (c0 > qi1 || c0 < qi1 - (WIN - 1)) s[am][bn][2] = -FLT_MAX;
                if (c1 > qi1 || c1 < qi1 - (WIN - 1)) s[am][bn][3] = -FLT_MAX;
            }
            float mx0 = -FLT_MAX, mx1 = -FLT_MAX;
#pragma unroll
            for (int bn = 0; bn < 8; bn++) {
                mx0 = fmaxf(mx0, fmaxf(s[am][bn][0], s[am][bn][1]));
                mx1 = fmaxf(mx1, fmaxf(s[am][bn][2], s[am][bn][3]));
            }
            mx0 = fmaxf(mx0, __shfl_xor_sync(0xffffffffu, mx0, 1));
            mx0 = fmaxf(mx0, __shfl_xor_sync(0xffffffffu, mx0, 2));
            mx1 = fmaxf(mx1, __shfl_xor_sync(0xffffffffu, mx1, 1));
            mx1 = fmaxf(mx1, __shfl_xor_sync(0xffffffffu, mx1, 2));
            float mn0 = fmaxf(mrow[am][0], mx0);
            float mn1 = fmaxf(mrow[am][1], mx1);
            float a0 = __expf(mrow[am][0] - mn0);
            float a1 = __expf(mrow[am][1] - mn1);
            mrow[am][0] = mn0; mrow[am][1] = mn1;
            float rs0 = 0.f, rs1 = 0.f;
#pragma unroll
            for (int bn = 0; bn < 8; bn++) {
                s[am][bn][0] = __expf(s[am][bn][0] - mn0);
                s[am][bn][1] = __expf(s[am][bn][1] - mn0);
                s[am][bn][2] = __expf(s[am][bn][2] - mn1);
                s[am][bn][3] = __expf(s[am][bn][3] - mn1);
                rs0 += s[am][bn][0] + s[am][bn][1];
                rs1 += s[am][bn][2] + s[am][bn][3];
            }
            rs0 += __shfl_xor_sync(0xffffffffu, rs0, 1);
            rs0 += __shfl_xor_sync(0xffffffffu, rs0, 2);
            rs1 += __shfl_xor_sync(0xffffffffu, rs1, 1);
            rs1 += __shfl_xor_sync(0xffffffffu, rs1, 2);
            lrow[am][0] = lrow[am][0] * a0 + rs0;
            lrow[am][1] = lrow[am][1] * a1 + rs1;
#pragma unroll
            for (int bn = 0; bn < 8; bn++) {
                o[am][bn][0] *= a0; o[am][bn][1] *= a0;
                o[am][bn][2] *= a1; o[am][bn][3] *= a1;
            }
        }

        uint32_t pf[2][4][4];
#pragma unroll
        for (int am = 0; am < 2; am++)
#pragma unroll
            for (int kk = 0; kk < 4; kk++) {
                pf[am][kk][0] = pack_f16(s[am][2*kk][0],   s[am][2*kk][1]);
                pf[am][kk][1] = pack_f16(s[am][2*kk][2],   s[am][2*kk][3]);
                pf[am][kk][2] = pack_f16(s[am][2*kk+1][0], s[am][2*kk+1][1]);
                pf[am][kk][3] = pack_f16(s[am][2*kk+1][2], s[am][2*kk+1][3]);
            }

#pragma unroll
        for (int kk = 0; kk < 4; kk++) {
            uint32_t vf[8][2];
#pragma unroll
            for (int g = 0; g < 4; g++) {
                uint32_t a = voff + kk * (16 * KVP * 2) + g * 32;
                uint32_t r[4];
                LDSM4T(r, vs_b + a);
                vf[2*g][0] = r[0]; vf[2*g][1] = r[1];
                vf[2*g+1][0] = r[2]; vf[2*g+1][1] = r[3];
            }
#pragma unroll
            for (int bn = 0; bn < 8; bn++)
#pragma unroll
                for (int am = 0; am < 2; am++)
                    mma_f16(o[am][bn], pf[am][kk], vf[bn]);
        }
    }

#pragma unroll
    for (int am = 0; am < 2; am++) {
        float inv0 = 1.f / lrow[am][0];
        float inv1 = 1.f / lrow[am][1];
        long r0 = rowb + i0 + wid * 32 + am * 16 + gid;
#pragma unroll
        for (int bn = 0; bn < 8; bn++) {
            int col = h * DH + bn * 8 + 2 * tig;
            *(uint32_t*)(ctx16 + r0 * DIM + col) =
                pack_f16(o[am][bn][0] * inv0, o[am][bn][1] * inv0);
            *(uint32_t*)(ctx16 + (r0 + 8) * DIM + col) =
                pack_f16(o[am][bn][2] * inv1, o[am][bn][3] * inv1);
        }
    }
}

// ---------------------------------------------------------------------------
extern "C" void kernel_launch(void* const* d_in, const int* in_sizes, int n_in,
                              void* d_out, int out_size)
{
    (void)in_sizes; (void)n_in; (void)out_size;
    const float* x    = (const float*)d_in[0];
    const float* Wqkv = (const float*)d_in[1];
    const float* Wout = (const float*)d_in[2];
    float* out = (float*)d_out;

    __half *x16, *wq, *wo, *qkv, *c16;
    cudaGetSymbolAddress((void**)&x16, g_x16);
    cudaGetSymbolAddress((void**)&wq,  g_wq);
    cudaGetSymbolAddress((void**)&wo,  g_wo);
    cudaGetSymbolAddress((void**)&qkv, g_qkv);
    cudaGetSymbolAddress((void**)&c16, g_c16);

    cudaFuncSetAttribute(gemm_1p<0>,
                         cudaFuncAttributeMaxDynamicSharedMemorySize, GEMM_SMEM);
    cudaFuncSetAttribute(gemm_1p<1>,
                         cudaFuncAttributeMaxDynamicSharedMemorySize, GEMM_SMEM);

    // prep
    convert_x_kernel<<<(MTOT * KD) / 1024, 256>>>(x, x16);
    tsplit_kernel<<<dim3(E3 / 32, KD / 32), dim3(32, 8)>>>(Wqkv, wq, E3, KD);
    tsplit_kernel<<<dim3(DIM / 32, KD / 32), dim3(32, 8)>>>(Wout, wo, DIM, KD);

    // 1) QKV projection (single pass, BK=64) -> plain fp16 qkv (Q pre-scaled)
    gemm_1p<1><<<dim3(E3 / 128, MTOT / 128), 256, GEMM_SMEM>>>(
        x16, wq, nullptr, qkv, MTOT, E3, KD, DIM);

    // 2) sliding-window attention (single pass) -> plain fp16 ctx
    attn_mma<<<dim3(SEQ / 128, NH, BATCH), 128>>>(qkv, c16);

    // 3) output projection (single pass, BK=64) -> fp32 out
    gemm_1p<0><<<dim3(DIM / 128, MTOT / 128), 256, GEMM_SMEM>>>(
        c16, wo, out, nullptr, MTOT, DIM, KD, 0);
}